// round 6
// baseline (speedup 1.0000x reference)
#include <cuda_runtime.h>
#include <cstdint>
#include <cmath>

// ===========================================================================
// Problem constants
// ===========================================================================
static constexpr int B_   = 4;
static constexpr int S_   = 1024;
static constexpr int D_   = 1024;
static constexpr int H_   = 16;
static constexpr int DH_  = 64;
static constexpr int E_   = 8;
static constexpr int FF1_ = 4096;
static constexpr int FF2_ = 2048;
static constexpr int NTOK = B_ * S_;        // 4096
static constexpr int KMOE2 = E_ * FF2_;     // 16384

// ===========================================================================
// Scratch
// ===========================================================================
__device__ float g_hn1   [(size_t)NTOK * D_];
__device__ float g_wqkvr [(size_t)3 * D_ * D_];
__device__ float g_woutr [(size_t)D_ * D_];
__device__ float g_qkv   [(size_t)NTOK * 3 * D_];
__device__ float g_vt    [(size_t)B_ * H_ * DH_ * S_];
__device__ float g_scores[(size_t)B_ * H_ * S_ * S_];
__device__ float g_attno [(size_t)NTOK * D_];
__device__ float g_h2    [(size_t)NTOK * D_];
__device__ float g_hn2   [(size_t)NTOK * D_];
__device__ float g_gate  [NTOK];
__device__ float g_w1t   [(size_t)E_ * FF1_ * D_];
__device__ float g_w2t   [(size_t)D_ * KMOE2];
__device__ float g_act   [(size_t)NTOK * KMOE2];

// ===========================================================================
// Helpers
// ===========================================================================
__device__ __forceinline__ uint32_t smem_u32(const void* p) {
    uint32_t a;
    asm("{ .reg .u64 t; cvta.to.shared.u64 t, %1; cvt.u32.u64 %0, t; }" : "=r"(a) : "l"(p));
    return a;
}
__device__ __forceinline__ float to_tf32(float x) {
    uint32_t u;
    asm("cvt.rna.tf32.f32 %0, %1;" : "=r"(u) : "f"(x));
    return __uint_as_float(u);
}

#define CP16(dst, src) \
    asm volatile("cp.async.cg.shared.global [%0], [%1], 16;" :: "r"(dst), "l"(src))
#define CP_COMMIT()  asm volatile("cp.async.commit_group;" ::: "memory")
#define CP_WAIT1()   asm volatile("cp.async.wait_group 1;" ::: "memory")
#define CP_WAIT0()   asm volatile("cp.async.wait_group 0;" ::: "memory")

__device__ __forceinline__ void mma_tf32(float& c0, float& c1, float& c2, float& c3,
                                         uint32_t a0, uint32_t a1, uint32_t a2, uint32_t a3,
                                         uint32_t b0, uint32_t b1)
{
    asm volatile(
        "mma.sync.aligned.m16n8k8.row.col.f32.tf32.tf32.f32 "
        "{%0,%1,%2,%3}, {%4,%5,%6,%7}, {%8,%9}, {%0,%1,%2,%3};"
        : "+f"(c0), "+f"(c1), "+f"(c2), "+f"(c3)
        : "r"(a0), "r"(a1), "r"(a2), "r"(a3), "r"(b0), "r"(b1));
}

// ===========================================================================
// mma.sync tf32 NT GEMM (128 x BN tile) — used for QK^T, PV, out-proj.
// ===========================================================================
template<int EPI, int BN, bool ROUND>
__global__ void __launch_bounds__(256)
mma_gemm(const float* __restrict__ A, const float* __restrict__ B,
         float* __restrict__ C, const float* __restrict__ Res,
         const float* __restrict__ Gvec,
         int M, int N, int K, int lda, int ldb, int ldc,
         int zDiv, long sA1, long sA2, long sB1, long sB2, long sC1, long sC2,
         float alpha)
{
    constexpr int NT = BN / 16;
    constexpr int ASTG = 128 * 36;
    constexpr int BSTG = BN * 36;

    extern __shared__ __align__(16) float sm[];
    const uint32_t sbase = smem_u32(sm);
    const int tid = threadIdx.x, wid = tid >> 5, lane = tid & 31;
    const int warp_m = wid & 3, warp_n = wid >> 2;

    const int bz = blockIdx.z;
    const int zb = bz / zDiv, zh = bz - zb * zDiv;
    A += (size_t)zb * sA1 + (size_t)zh * sA2;
    B += (size_t)zb * sB1 + (size_t)zh * sB2;
    const size_t coff = (size_t)zb * sC1 + (size_t)zh * sC2;
    C += coff;
    if (EPI == 1 || EPI == 2) Res += coff;

    const int bm = blockIdx.y * 128;
    const int bn = blockIdx.x * BN;
    A += (size_t)bm * lda;
    B += (size_t)bn * ldb;

    const int nk = K / 32;

    auto loadA = [&](int s, int kt) {
        const float* base = A + kt * 32;
        const uint32_t dbase = sbase + (uint32_t)(s * ASTG) * 4;
        #pragma unroll
        for (int i = 0; i < 4; i++) {
            const int c = tid + i * 256;
            const int row = c >> 3, kc = c & 7;
            CP16(dbase + (uint32_t)row * 144 + (uint32_t)kc * 16,
                 base + (size_t)row * lda + kc * 4);
        }
    };
    auto loadB = [&](int s, int kt) {
        const float* base = B + kt * 32;
        const uint32_t dbase = sbase + (uint32_t)(2 * ASTG + s * BSTG) * 4;
        #pragma unroll
        for (int i = 0; i < BN / 32; i++) {
            const int c = tid + i * 256;
            const int row = c >> 3, kc = c & 7;
            CP16(dbase + (uint32_t)row * 144 + (uint32_t)kc * 16,
                 base + (size_t)row * ldb + kc * 4);
        }
    };

    float acc[2][NT][4];
    #pragma unroll
    for (int mi = 0; mi < 2; mi++)
        #pragma unroll
        for (int ni = 0; ni < NT; ni++)
            #pragma unroll
            for (int j = 0; j < 4; j++) acc[mi][ni][j] = 0.f;

    loadA(0, 0); loadB(0, 0); CP_COMMIT();

    const int lq = lane >> 2;
    const int lr = lane & 3;

    for (int kt = 0; kt < nk; kt++) {
        const int cs = kt & 1;
        if (kt + 1 < nk) {
            loadA(cs ^ 1, kt + 1); loadB(cs ^ 1, kt + 1); CP_COMMIT();
            CP_WAIT1();
        } else {
            CP_WAIT0();
        }
        __syncthreads();

        const float* As = sm + cs * ASTG;
        const float* Bs = sm + 2 * ASTG + cs * BSTG;

        #pragma unroll
        for (int ks = 0; ks < 4; ks++) {
            const int kk = ks * 8 + lr;
            uint32_t a[2][4];
            #pragma unroll
            for (int mi = 0; mi < 2; mi++) {
                const int r0 = warp_m * 32 + mi * 16 + lq;
                a[mi][0] = __float_as_uint(As[r0 * 36 + kk]);
                a[mi][1] = __float_as_uint(As[(r0 + 8) * 36 + kk]);
                a[mi][2] = __float_as_uint(As[r0 * 36 + kk + 4]);
                a[mi][3] = __float_as_uint(As[(r0 + 8) * 36 + kk + 4]);
            }
            uint32_t b[NT][2];
            #pragma unroll
            for (int ni = 0; ni < NT; ni++) {
                const int n0 = warp_n * (BN / 2) + ni * 8 + lq;
                b[ni][0] = __float_as_uint(Bs[n0 * 36 + kk]);
                b[ni][1] = __float_as_uint(Bs[n0 * 36 + kk + 4]);
            }
            #pragma unroll
            for (int mi = 0; mi < 2; mi++)
                #pragma unroll
                for (int ni = 0; ni < NT; ni++)
                    mma_tf32(acc[mi][ni][0], acc[mi][ni][1], acc[mi][ni][2], acc[mi][ni][3],
                             a[mi][0], a[mi][1], a[mi][2], a[mi][3],
                             b[ni][0], b[ni][1]);
        }
        __syncthreads();
    }

    #pragma unroll
    for (int mi = 0; mi < 2; mi++) {
        const int row0 = bm + warp_m * 32 + mi * 16 + lq;
        float gv0 = 1.f, gv1 = 1.f;
        if (EPI == 2) { gv0 = Gvec[row0]; gv1 = Gvec[row0 + 8]; }
        #pragma unroll
        for (int ni = 0; ni < NT; ni++) {
            const int col = bn + warp_n * (BN / 2) + ni * 8 + lr * 2;
            const size_t i0 = (size_t)row0 * ldc + col;
            const size_t i1 = (size_t)(row0 + 8) * ldc + col;
            float2 o0, o1;
            if (EPI == 0) {
                o0.x = alpha * acc[mi][ni][0]; o0.y = alpha * acc[mi][ni][1];
                o1.x = alpha * acc[mi][ni][2]; o1.y = alpha * acc[mi][ni][3];
                if (ROUND) {
                    o0.x = to_tf32(o0.x); o0.y = to_tf32(o0.y);
                    o1.x = to_tf32(o1.x); o1.y = to_tf32(o1.y);
                }
            } else if (EPI == 1) {
                float2 r0 = *(const float2*)&Res[i0];
                float2 r1 = *(const float2*)&Res[i1];
                o0.x = acc[mi][ni][0] + r0.x; o0.y = acc[mi][ni][1] + r0.y;
                o1.x = acc[mi][ni][2] + r1.x; o1.y = acc[mi][ni][3] + r1.y;
            } else {
                float2 r0 = *(const float2*)&Res[i0];
                float2 r1 = *(const float2*)&Res[i1];
                o0.x = r0.x + acc[mi][ni][0] * gv0; o0.y = r0.y + acc[mi][ni][1] * gv0;
                o1.x = r1.x + acc[mi][ni][2] * gv1; o1.y = r1.y + acc[mi][ni][3] * gv1;
            }
            *(float2*)&C[i0] = o0;
            *(float2*)&C[i1] = o1;
        }
    }
}

// ===========================================================================
// BIG-TILE mma.sync tf32 NT GEMM: 256 x 128 block, 8 warps, warp tile 64x64.
// LDS:HMMA ratio 1:1 (vs 1.5:1 in 128-tile) — smem-crossbar relief.
//   EPI 0: C = alpha*acc (ROUND optional)    EPI 2: C = Res + acc*Gvec[row]
// ===========================================================================
template<int EPI, bool ROUND>
__global__ void __launch_bounds__(256)
mma_gemm256(const float* __restrict__ A, const float* __restrict__ B,
            float* __restrict__ C, const float* __restrict__ Res,
            const float* __restrict__ Gvec,
            int K, int lda, int ldb, int ldc, float alpha)
{
    constexpr int ASTG = 256 * 36;
    constexpr int BSTG = 128 * 36;

    extern __shared__ __align__(16) float sm[];
    const uint32_t sbase = smem_u32(sm);
    const int tid = threadIdx.x, wid = tid >> 5, lane = tid & 31;
    const int warp_m = wid & 3, warp_n = wid >> 2;

    const int bm = blockIdx.y * 256;
    const int bn = blockIdx.x * 128;
    A += (size_t)bm * lda;
    B += (size_t)bn * ldb;

    const int nk = K / 32;

    auto loadA = [&](int s, int kt) {
        const float* base = A + kt * 32;
        const uint32_t dbase = sbase + (uint32_t)(s * ASTG) * 4;
        #pragma unroll
        for (int i = 0; i < 8; i++) {
            const int c = tid + i * 256;          // 0..2047
            const int row = c >> 3, kc = c & 7;
            CP16(dbase + (uint32_t)row * 144 + (uint32_t)kc * 16,
                 base + (size_t)row * lda + kc * 4);
        }
    };
    auto loadB = [&](int s, int kt) {
        const float* base = B + kt * 32;
        const uint32_t dbase = sbase + (uint32_t)(2 * ASTG + s * BSTG) * 4;
        #pragma unroll
        for (int i = 0; i < 4; i++) {
            const int c = tid + i * 256;
            const int row = c >> 3, kc = c & 7;
            CP16(dbase + (uint32_t)row * 144 + (uint32_t)kc * 16,
                 base + (size_t)row * ldb + kc * 4);
        }
    };

    float acc[4][8][4];
    #pragma unroll
    for (int mi = 0; mi < 4; mi++)
        #pragma unroll
        for (int ni = 0; ni < 8; ni++)
            #pragma unroll
            for (int j = 0; j < 4; j++) acc[mi][ni][j] = 0.f;

    loadA(0, 0); loadB(0, 0); CP_COMMIT();

    const int lq = lane >> 2;
    const int lr = lane & 3;

    for (int kt = 0; kt < nk; kt++) {
        const int cs = kt & 1;
        if (kt + 1 < nk) {
            loadA(cs ^ 1, kt + 1); loadB(cs ^ 1, kt + 1); CP_COMMIT();
            CP_WAIT1();
        } else {
            CP_WAIT0();
        }
        __syncthreads();

        const float* As = sm + cs * ASTG;
        const float* Bs = sm + 2 * ASTG + cs * BSTG;

        #pragma unroll
        for (int ks = 0; ks < 4; ks++) {
            const int kk = ks * 8 + lr;
            uint32_t a[4][4];
            #pragma unroll
            for (int mi = 0; mi < 4; mi++) {
                const int r0 = warp_m * 64 + mi * 16 + lq;
                a[mi][0] = __float_as_uint(As[r0 * 36 + kk]);
                a[mi][1] = __float_as_uint(As[(r0 + 8) * 36 + kk]);
                a[mi][2] = __float_as_uint(As[r0 * 36 + kk + 4]);
                a[mi][3] = __float_as_uint(As[(r0 + 8) * 36 + kk + 4]);
            }
            uint32_t b[8][2];
            #pragma unroll
            for (int ni = 0; ni < 8; ni++) {
                const int n0 = warp_n * 64 + ni * 8 + lq;
                b[ni][0] = __float_as_uint(Bs[n0 * 36 + kk]);
                b[ni][1] = __float_as_uint(Bs[n0 * 36 + kk + 4]);
            }
            #pragma unroll
            for (int mi = 0; mi < 4; mi++)
                #pragma unroll
                for (int ni = 0; ni < 8; ni++)
                    mma_tf32(acc[mi][ni][0], acc[mi][ni][1], acc[mi][ni][2], acc[mi][ni][3],
                             a[mi][0], a[mi][1], a[mi][2], a[mi][3],
                             b[ni][0], b[ni][1]);
        }
        __syncthreads();
    }

    #pragma unroll
    for (int mi = 0; mi < 4; mi++) {
        const int row0 = bm + warp_m * 64 + mi * 16 + lq;
        float gv0 = 1.f, gv1 = 1.f;
        if (EPI == 2) { gv0 = Gvec[row0]; gv1 = Gvec[row0 + 8]; }
        #pragma unroll
        for (int ni = 0; ni < 8; ni++) {
            const int col = bn + warp_n * 64 + ni * 8 + lr * 2;
            const size_t i0 = (size_t)row0 * ldc + col;
            const size_t i1 = (size_t)(row0 + 8) * ldc + col;
            float2 o0, o1;
            if (EPI == 0) {
                o0.x = alpha * acc[mi][ni][0]; o0.y = alpha * acc[mi][ni][1];
                o1.x = alpha * acc[mi][ni][2]; o1.y = alpha * acc[mi][ni][3];
                if (ROUND) {
                    o0.x = to_tf32(o0.x); o0.y = to_tf32(o0.y);
                    o1.x = to_tf32(o1.x); o1.y = to_tf32(o1.y);
                }
            } else {
                float2 r0 = *(const float2*)&Res[i0];
                float2 r1 = *(const float2*)&Res[i1];
                o0.x = r0.x + acc[mi][ni][0] * gv0; o0.y = r0.y + acc[mi][ni][1] * gv0;
                o1.x = r1.x + acc[mi][ni][2] * gv1; o1.y = r1.y + acc[mi][ni][3] * gv1;
            }
            *(float2*)&C[i0] = o0;
            *(float2*)&C[i1] = o1;
        }
    }
}

// ===========================================================================
// Fused MoE1 + SwiGLU, big tile: 256 tokens x 64 act-cols per CTA.
// B tile (128 rows) interleaves a/b halves by 8-row groups; within each
// warp, even ni = 'a', odd ni = 'b' at matching lanes.
// Grid: (FF2/64, NTOK/256, E)
// ===========================================================================
__global__ void __launch_bounds__(256)
moe1_swiglu256(const float* __restrict__ hn2, const float* __restrict__ w1t,
               float* __restrict__ act)
{
    constexpr int ASTG = 256 * 36;
    constexpr int BSTG = 128 * 36;

    extern __shared__ __align__(16) float sm[];
    const uint32_t sbase = smem_u32(sm);
    const int tid = threadIdx.x, wid = tid >> 5, lane = tid & 31;
    const int warp_m = wid & 3, warp_n = wid >> 2;

    const int e    = blockIdx.z;
    const int bn_a = blockIdx.x * 64;
    const int bm   = blockIdx.y * 256;

    const float* A  = hn2 + (size_t)bm * D_;
    const float* Be = w1t + (size_t)e * FF1_ * D_;

    const int nk = D_ / 32;

    auto loadA = [&](int s, int kt) {
        const float* base = A + kt * 32;
        const uint32_t dbase = sbase + (uint32_t)(s * ASTG) * 4;
        #pragma unroll
        for (int i = 0; i < 8; i++) {
            const int c = tid + i * 256;
            const int row = c >> 3, kc = c & 7;
            CP16(dbase + (uint32_t)row * 144 + (uint32_t)kc * 16,
                 base + (size_t)row * D_ + kc * 4);
        }
    };
    auto loadB = [&](int s, int kt) {
        const uint32_t dbase = sbase + (uint32_t)(2 * ASTG + s * BSTG) * 4;
        #pragma unroll
        for (int i = 0; i < 4; i++) {
            const int c = tid + i * 256;
            const int row = c >> 3, kc = c & 7;
            const int half = (row >> 3) & 1;
            const int coll = ((row >> 4) << 3) + (row & 7);
            const int wrow = bn_a + coll + half * FF2_;
            CP16(dbase + (uint32_t)row * 144 + (uint32_t)kc * 16,
                 Be + (size_t)wrow * D_ + kt * 32 + kc * 4);
        }
    };

    float acc[4][8][4];
    #pragma unroll
    for (int mi = 0; mi < 4; mi++)
        #pragma unroll
        for (int ni = 0; ni < 8; ni++)
            #pragma unroll
            for (int j = 0; j < 4; j++) acc[mi][ni][j] = 0.f;

    loadA(0, 0); loadB(0, 0); CP_COMMIT();

    const int lq = lane >> 2;
    const int lr = lane & 3;

    for (int kt = 0; kt < nk; kt++) {
        const int cs = kt & 1;
        if (kt + 1 < nk) {
            loadA(cs ^ 1, kt + 1); loadB(cs ^ 1, kt + 1); CP_COMMIT();
            CP_WAIT1();
        } else {
            CP_WAIT0();
        }
        __syncthreads();

        const float* As = sm + cs * ASTG;
        const float* Bs = sm + 2 * ASTG + cs * BSTG;

        #pragma unroll
        for (int ks = 0; ks < 4; ks++) {
            const int kk = ks * 8 + lr;
            uint32_t a[4][4];
            #pragma unroll
            for (int mi = 0; mi < 4; mi++) {
                const int r0 = warp_m * 64 + mi * 16 + lq;
                a[mi][0] = __float_as_uint(As[r0 * 36 + kk]);
                a[mi][1] = __float_as_uint(As[(r0 + 8) * 36 + kk]);
                a[mi][2] = __float_as_uint(As[r0 * 36 + kk + 4]);
                a[mi][3] = __float_as_uint(As[(r0 + 8) * 36 + kk + 4]);
            }
            uint32_t b[8][2];
            #pragma unroll
            for (int ni = 0; ni < 8; ni++) {
                const int n0 = warp_n * 64 + ni * 8 + lq;
                b[ni][0] = __float_as_uint(Bs[n0 * 36 + kk]);
                b[ni][1] = __float_as_uint(Bs[n0 * 36 + kk + 4]);
            }
            #pragma unroll
            for (int mi = 0; mi < 4; mi++)
                #pragma unroll
                for (int ni = 0; ni < 8; ni++)
                    mma_tf32(acc[mi][ni][0], acc[mi][ni][1], acc[mi][ni][2], acc[mi][ni][3],
                             a[mi][0], a[mi][1], a[mi][2], a[mi][3],
                             b[ni][0], b[ni][1]);
        }
        __syncthreads();
    }

    // ---- epilogue: act = tf32(a * silu(b))
    #pragma unroll
    for (int mi = 0; mi < 4; mi++) {
        const int row0 = bm + warp_m * 64 + mi * 16 + lq;
        #pragma unroll
        for (int p = 0; p < 4; p++) {
            const float* av = acc[mi][2 * p];
            const float* bv = acc[mi][2 * p + 1];
            float2 o0, o1;
            o0.x = to_tf32(av[0] * bv[0] / (1.f + __expf(-bv[0])));
            o0.y = to_tf32(av[1] * bv[1] / (1.f + __expf(-bv[1])));
            o1.x = to_tf32(av[2] * bv[2] / (1.f + __expf(-bv[2])));
            o1.y = to_tf32(av[3] * bv[3] / (1.f + __expf(-bv[3])));
            const int col = e * FF2_ + bn_a + warp_n * 32 + p * 8 + lr * 2;
            *(float2*)&act[(size_t)row0 * KMOE2 + col] = o0;
            *(float2*)&act[(size_t)(row0 + 8) * KMOE2 + col] = o1;
        }
    }
}

// ===========================================================================
// RMSNorm (rounds output to tf32)
// ===========================================================================
__global__ void rmsnorm_k(const float* __restrict__ x, const float* __restrict__ w,
                          float* __restrict__ y, float eps)
{
    const int row = blockIdx.x;
    const float* xr = x + (size_t)row * D_;
    float v[4];
    float s = 0.f;
    #pragma unroll
    for (int i = 0; i < 4; i++) { v[i] = xr[threadIdx.x + 256 * i]; s += v[i] * v[i]; }
    #pragma unroll
    for (int o = 16; o > 0; o >>= 1) s += __shfl_xor_sync(~0u, s, o);
    __shared__ float red[8];
    if ((threadIdx.x & 31) == 0) red[threadIdx.x >> 5] = s;
    __syncthreads();
    if (threadIdx.x < 8) {
        float t = red[threadIdx.x];
        #pragma unroll
        for (int o = 4; o > 0; o >>= 1) t += __shfl_xor_sync(0xffu, t, o);
        if (threadIdx.x == 0) red[0] = t;
    }
    __syncthreads();
    const float inv = rsqrtf(red[0] / (float)D_ + eps);
    float* yr = y + (size_t)row * D_;
    #pragma unroll
    for (int i = 0; i < 4; i++)
        yr[threadIdx.x + 256 * i] = to_tf32(v[i] * inv * w[threadIdx.x + 256 * i]);
}

// ===========================================================================
// Softmax over 1024-length rows
// ===========================================================================
__global__ void softmax_k(float* __restrict__ sc)
{
    float* p = sc + (size_t)blockIdx.x * S_;
    const int t = threadIdx.x;
    float v[4];
    #pragma unroll
    for (int i = 0; i < 4; i++) v[i] = p[t + 256 * i];
    float m = fmaxf(fmaxf(v[0], v[1]), fmaxf(v[2], v[3]));
    #pragma unroll
    for (int o = 16; o > 0; o >>= 1) m = fmaxf(m, __shfl_xor_sync(~0u, m, o));
    __shared__ float red[8];
    if ((t & 31) == 0) red[t >> 5] = m;
    __syncthreads();
    float mm = fmaxf(fmaxf(red[0], red[1]), fmaxf(red[2], red[3]));
    mm = fmaxf(mm, fmaxf(fmaxf(red[4], red[5]), fmaxf(red[6], red[7])));
    float s = 0.f;
    #pragma unroll
    for (int i = 0; i < 4; i++) { v[i] = __expf(v[i] - mm); s += v[i]; }
    #pragma unroll
    for (int o = 16; o > 0; o >>= 1) s += __shfl_xor_sync(~0u, s, o);
    __syncthreads();
    if ((t & 31) == 0) red[t >> 5] = s;
    __syncthreads();
    float ss = red[0] + red[1] + red[2] + red[3] + red[4] + red[5] + red[6] + red[7];
    const float inv = 1.f / ss;
    #pragma unroll
    for (int i = 0; i < 4; i++) p[t + 256 * i] = to_tf32(v[i] * inv);
}

// ===========================================================================
// Gating — from raw fp32 h2
// ===========================================================================
__global__ void gate_k(const float* __restrict__ h2, const float* __restrict__ n2w,
                       const float* __restrict__ gw,
                       const float* __restrict__ gb, const float* __restrict__ grw,
                       float* __restrict__ g)
{
    const int n    = blockIdx.x * 4 + (threadIdx.x >> 5);
    const int lane = threadIdx.x & 31;
    const float* xr = h2 + (size_t)n * D_;
    float acc[E_];
    float ssx = 0.f;
    #pragma unroll
    for (int e = 0; e < E_; e++) acc[e] = 0.f;
    for (int d = lane; d < D_; d += 32) {
        const float xv = xr[d];
        ssx += xv * xv;
        const float xw = xv * n2w[d];
        #pragma unroll
        for (int e = 0; e < E_; e++) acc[e] += xw * gw[e * D_ + d];
    }
    #pragma unroll
    for (int o = 16; o > 0; o >>= 1) ssx += __shfl_xor_sync(~0u, ssx, o);
    #pragma unroll
    for (int e = 0; e < E_; e++)
        #pragma unroll
        for (int o = 16; o > 0; o >>= 1) acc[e] += __shfl_xor_sync(~0u, acc[e], o);
    if (lane == 0) {
        const float invr = rsqrtf(ssx / (float)D_ + 1e-8f);
        float l[E_], ss = 0.f;
        #pragma unroll
        for (int e = 0; e < E_; e++) { l[e] = acc[e] * invr + gb[e]; ss += l[e] * l[e]; }
        const float inv = rsqrtf(ss / (float)E_ + 1.1920929e-7f);
        float m = -INFINITY;
        #pragma unroll
        for (int e = 0; e < E_; e++) { l[e] = l[e] * inv * grw[e] * 2.0f; m = fmaxf(m, l[e]); }
        float sum = 0.f, mx = 0.f;
        #pragma unroll
        for (int e = 0; e < E_; e++) {
            const float ex = __expf(l[e] - m);
            sum += ex; mx = fmaxf(mx, ex);
        }
        const float top = mx / sum;
        g[n] = top / (top + 1e-6f);
    }
}

// ===========================================================================
// Batched transpose: out[z][c][r] = tf32(in[z][r][c])
// ===========================================================================
__global__ void transpose_k(const float* __restrict__ in, float* __restrict__ out,
                            int ldin, int ldout,
                            int zDiv, long zi1, long zi2, long zo1, long zo2)
{
    __shared__ float t[32][33];
    const int z = blockIdx.z;
    const int zb = z / zDiv, zh = z - zb * zDiv;
    in  += (size_t)zb * zi1 + (size_t)zh * zi2;
    out += (size_t)zb * zo1 + (size_t)zh * zo2;
    const int c0 = blockIdx.x * 32, r0 = blockIdx.y * 32;
    #pragma unroll
    for (int i = 0; i < 4; i++)
        t[threadIdx.y + i * 8][threadIdx.x] =
            in[(size_t)(r0 + threadIdx.y + i * 8) * ldin + c0 + threadIdx.x];
    __syncthreads();
    #pragma unroll
    for (int i = 0; i < 4; i++)
        out[(size_t)(c0 + threadIdx.y + i * 8) * ldout + r0 + threadIdx.x] =
            to_tf32(t[threadIdx.x][threadIdx.y + i * 8]);
}

// ===========================================================================
// Round-copy to tf32
// ===========================================================================
__global__ void roundcpy_k(const float* __restrict__ in, float* __restrict__ out, int n)
{
    for (int i = blockIdx.x * blockDim.x + threadIdx.x; i < n; i += gridDim.x * blockDim.x)
        out[i] = to_tf32(in[i]);
}

// ===========================================================================
// Launch
// ===========================================================================
static inline int smem_bytes(int bn)  { return (2 * 128 * 36 + 2 * bn * 36) * 4; }
static inline int smem_bytes256()     { return (2 * 256 * 36 + 2 * 128 * 36) * 4; }   // 110592

extern "C" void kernel_launch(void* const* d_in, const int* in_sizes, int n_in,
                              void* d_out, int out_size)
{
    const float* x      = (const float*)d_in[0];
    const float* w_qkv  = (const float*)d_in[1];
    const float* w_out  = (const float*)d_in[2];
    const float* norm1w = (const float*)d_in[3];
    const float* norm2w = (const float*)d_in[4];
    const float* gate_w = (const float*)d_in[5];
    const float* gate_b = (const float*)d_in[6];
    const float* gate_rw= (const float*)d_in[7];
    const float* w1     = (const float*)d_in[8];
    const float* w2     = (const float*)d_in[9];
    float* out = (float*)d_out;

    float *hn1, *wqkvr, *woutr, *qkv, *vt, *scores, *attno, *h2, *hn2, *gate, *w1t, *w2t, *act;
    cudaGetSymbolAddress((void**)&hn1,    g_hn1);
    cudaGetSymbolAddress((void**)&wqkvr,  g_wqkvr);
    cudaGetSymbolAddress((void**)&woutr,  g_woutr);
    cudaGetSymbolAddress((void**)&qkv,    g_qkv);
    cudaGetSymbolAddress((void**)&vt,     g_vt);
    cudaGetSymbolAddress((void**)&scores, g_scores);
    cudaGetSymbolAddress((void**)&attno,  g_attno);
    cudaGetSymbolAddress((void**)&h2,     g_h2);
    cudaGetSymbolAddress((void**)&hn2,    g_hn2);
    cudaGetSymbolAddress((void**)&gate,   g_gate);
    cudaGetSymbolAddress((void**)&w1t,    g_w1t);
    cudaGetSymbolAddress((void**)&w2t,    g_w2t);
    cudaGetSymbolAddress((void**)&act,    g_act);

    cudaFuncSetAttribute(mma_gemm<0,128,true >, cudaFuncAttributeMaxDynamicSharedMemorySize, smem_bytes(128));
    cudaFuncSetAttribute(mma_gemm<0, 64,true >, cudaFuncAttributeMaxDynamicSharedMemorySize, smem_bytes(64));
    cudaFuncSetAttribute(mma_gemm<1,128,false>, cudaFuncAttributeMaxDynamicSharedMemorySize, smem_bytes(128));
    cudaFuncSetAttribute(mma_gemm256<0,true >, cudaFuncAttributeMaxDynamicSharedMemorySize, smem_bytes256());
    cudaFuncSetAttribute(mma_gemm256<2,false>, cudaFuncAttributeMaxDynamicSharedMemorySize, smem_bytes256());
    cudaFuncSetAttribute(moe1_swiglu256,       cudaFuncAttributeMaxDynamicSharedMemorySize, smem_bytes256());

    // --- weight prep ---
    roundcpy_k<<<2048, 256>>>(w_qkv, wqkvr, 3 * D_ * D_);
    roundcpy_k<<<1024, 256>>>(w_out, woutr, D_ * D_);
    transpose_k<<<dim3(FF1_ / 32, D_ / 32, E_), dim3(32, 8)>>>(
        w1, w1t, FF1_, D_, 1, (long)D_ * FF1_, 0, (long)D_ * FF1_, 0);
    transpose_k<<<dim3(D_ / 32, KMOE2 / 32, 1), dim3(32, 8)>>>(
        w2, w2t, D_, KMOE2, 1, 0, 0, 0, 0);

    // --- 1) rmsnorm1 ---
    rmsnorm_k<<<NTOK, 256>>>(x, norm1w, hn1, 1e-8f);

    // --- 2) QKV (big tile) ---
    mma_gemm256<0,true><<<dim3(3 * D_ / 128, NTOK / 256, 1), 256, smem_bytes256()>>>(
        hn1, wqkvr, qkv, nullptr, nullptr,
        D_, D_, D_, 3 * D_, 1.f);

    // --- 3) V transpose ---
    transpose_k<<<dim3(DH_ / 32, S_ / 32, B_ * H_), dim3(32, 8)>>>(
        qkv + 2 * D_, vt, 3 * D_, S_,
        H_, (long)S_ * 3 * D_, (long)DH_,
        (long)H_ * DH_ * S_, (long)DH_ * S_);

    // --- 4) scores = Q K^T / 8 ---
    mma_gemm<0,128,true><<<dim3(S_ / 128, S_ / 128, B_ * H_), 256, smem_bytes(128)>>>(
        qkv, qkv + D_, scores, nullptr, nullptr,
        S_, S_, DH_, 3 * D_, 3 * D_, S_,
        H_,
        (long)S_ * 3 * D_, (long)DH_,
        (long)S_ * 3 * D_, (long)DH_,
        (long)H_ * S_ * S_, (long)S_ * S_,
        0.125f);

    // --- 5) softmax ---
    softmax_k<<<B_ * H_ * S_, 256>>>(scores);

    // --- 6) O = P V ---
    mma_gemm<0,64,true><<<dim3(1, S_ / 128, B_ * H_), 256, smem_bytes(64)>>>(
        scores, vt, attno, nullptr, nullptr,
        S_, DH_, S_, S_, S_, D_,
        H_,
        (long)H_ * S_ * S_, (long)S_ * S_,
        (long)H_ * DH_ * S_, (long)DH_ * S_,
        (long)S_ * D_, (long)DH_,
        1.f);

    // --- 7) h2 = x + O w_out^T ---
    mma_gemm<1,128,false><<<dim3(D_ / 128, NTOK / 128, 1), 256, smem_bytes(128)>>>(
        attno, woutr, h2, x, nullptr,
        NTOK, D_, D_, D_, D_, D_,
        1, 0, 0, 0, 0, 0, 0, 1.f);

    // --- 8) rmsnorm2 + gate ---
    rmsnorm_k<<<NTOK, 256>>>(h2, norm2w, hn2, 1e-8f);
    gate_k<<<NTOK / 4, 128>>>(h2, norm2w, gate_w, gate_b, gate_rw, gate);

    // --- 9+10) fused MoE1 + SwiGLU (big tile) -> act [4096, 16384] ---
    moe1_swiglu256<<<dim3(FF2_ / 64, NTOK / 256, E_), 256, smem_bytes256()>>>(
        hn2, w1t, act);

    // --- 11) MoE2 (big tile): out = h2 + (act x w2t^T) * g[n] ---
    mma_gemm256<2,false><<<dim3(D_ / 128, NTOK / 256, 1), 256, smem_bytes256()>>>(
        act, w2t, out, h2, gate,
        KMOE2, KMOE2, KMOE2, D_, 1.f);

    (void)in_sizes; (void)n_in; (void)out_size;
}

// round 7
// speedup vs baseline: 1.0671x; 1.0671x over previous
#include <cuda_runtime.h>
#include <cstdint>
#include <cmath>

// ===========================================================================
// Problem constants
// ===========================================================================
static constexpr int B_   = 4;
static constexpr int S_   = 1024;
static constexpr int D_   = 1024;
static constexpr int H_   = 16;
static constexpr int DH_  = 64;
static constexpr int E_   = 8;
static constexpr int FF1_ = 4096;
static constexpr int FF2_ = 2048;
static constexpr int NTOK = B_ * S_;        // 4096
static constexpr int KMOE2 = E_ * FF2_;     // 16384

// ===========================================================================
// Scratch
// ===========================================================================
__device__ float g_hn1   [(size_t)NTOK * D_];
__device__ float g_wqkvr [(size_t)3 * D_ * D_];
__device__ float g_woutr [(size_t)D_ * D_];
__device__ float g_qkv   [(size_t)NTOK * 3 * D_];
__device__ float g_vt    [(size_t)B_ * H_ * DH_ * S_];
__device__ float g_attno [(size_t)NTOK * D_];
__device__ float g_h2    [(size_t)NTOK * D_];
__device__ float g_hn2   [(size_t)NTOK * D_];
__device__ float g_gate  [NTOK];
__device__ float g_w1t   [(size_t)E_ * FF1_ * D_];
__device__ float g_w2t   [(size_t)D_ * KMOE2];
__device__ float g_act   [(size_t)NTOK * KMOE2];

// ===========================================================================
// Helpers
// ===========================================================================
__device__ __forceinline__ uint32_t smem_u32(const void* p) {
    uint32_t a;
    asm("{ .reg .u64 t; cvta.to.shared.u64 t, %1; cvt.u32.u64 %0, t; }" : "=r"(a) : "l"(p));
    return a;
}
__device__ __forceinline__ float to_tf32(float x) {
    uint32_t u;
    asm("cvt.rna.tf32.f32 %0, %1;" : "=r"(u) : "f"(x));
    return __uint_as_float(u);
}

#define CP16(dst, src) \
    asm volatile("cp.async.cg.shared.global [%0], [%1], 16;" :: "r"(dst), "l"(src))
#define CP_COMMIT()  asm volatile("cp.async.commit_group;" ::: "memory")
#define CP_WAIT1()   asm volatile("cp.async.wait_group 1;" ::: "memory")
#define CP_WAIT0()   asm volatile("cp.async.wait_group 0;" ::: "memory")

__device__ __forceinline__ void mma_tf32(float& c0, float& c1, float& c2, float& c3,
                                         uint32_t a0, uint32_t a1, uint32_t a2, uint32_t a3,
                                         uint32_t b0, uint32_t b1)
{
    asm volatile(
        "mma.sync.aligned.m16n8k8.row.col.f32.tf32.tf32.f32 "
        "{%0,%1,%2,%3}, {%4,%5,%6,%7}, {%8,%9}, {%0,%1,%2,%3};"
        : "+f"(c0), "+f"(c1), "+f"(c2), "+f"(c3)
        : "r"(a0), "r"(a1), "r"(a2), "r"(a3), "r"(b0), "r"(b1));
}

// ===========================================================================
// mma.sync tf32 NT GEMM (128 x BN tile)
// ===========================================================================
template<int EPI, int BN, bool ROUND>
__global__ void __launch_bounds__(256)
mma_gemm(const float* __restrict__ A, const float* __restrict__ B,
         float* __restrict__ C, const float* __restrict__ Res,
         const float* __restrict__ Gvec,
         int M, int N, int K, int lda, int ldb, int ldc,
         int zDiv, long sA1, long sA2, long sB1, long sB2, long sC1, long sC2,
         float alpha)
{
    constexpr int NT = BN / 16;
    constexpr int ASTG = 128 * 36;
    constexpr int BSTG = BN * 36;

    extern __shared__ __align__(16) float sm[];
    const uint32_t sbase = smem_u32(sm);
    const int tid = threadIdx.x, wid = tid >> 5, lane = tid & 31;
    const int warp_m = wid & 3, warp_n = wid >> 2;

    const int bz = blockIdx.z;
    const int zb = bz / zDiv, zh = bz - zb * zDiv;
    A += (size_t)zb * sA1 + (size_t)zh * sA2;
    B += (size_t)zb * sB1 + (size_t)zh * sB2;
    const size_t coff = (size_t)zb * sC1 + (size_t)zh * sC2;
    C += coff;
    if (EPI == 1 || EPI == 2) Res += coff;

    const int bm = blockIdx.y * 128;
    const int bn = blockIdx.x * BN;
    A += (size_t)bm * lda;
    B += (size_t)bn * ldb;

    const int nk = K / 32;

    auto loadA = [&](int s, int kt) {
        const float* base = A + kt * 32;
        const uint32_t dbase = sbase + (uint32_t)(s * ASTG) * 4;
        #pragma unroll
        for (int i = 0; i < 4; i++) {
            const int c = tid + i * 256;
            const int row = c >> 3, kc = c & 7;
            CP16(dbase + (uint32_t)row * 144 + (uint32_t)kc * 16,
                 base + (size_t)row * lda + kc * 4);
        }
    };
    auto loadB = [&](int s, int kt) {
        const float* base = B + kt * 32;
        const uint32_t dbase = sbase + (uint32_t)(2 * ASTG + s * BSTG) * 4;
        #pragma unroll
        for (int i = 0; i < BN / 32; i++) {
            const int c = tid + i * 256;
            const int row = c >> 3, kc = c & 7;
            CP16(dbase + (uint32_t)row * 144 + (uint32_t)kc * 16,
                 base + (size_t)row * ldb + kc * 4);
        }
    };

    float acc[2][NT][4];
    #pragma unroll
    for (int mi = 0; mi < 2; mi++)
        #pragma unroll
        for (int ni = 0; ni < NT; ni++)
            #pragma unroll
            for (int j = 0; j < 4; j++) acc[mi][ni][j] = 0.f;

    loadA(0, 0); loadB(0, 0); CP_COMMIT();

    const int lq = lane >> 2;
    const int lr = lane & 3;

    for (int kt = 0; kt < nk; kt++) {
        const int cs = kt & 1;
        if (kt + 1 < nk) {
            loadA(cs ^ 1, kt + 1); loadB(cs ^ 1, kt + 1); CP_COMMIT();
            CP_WAIT1();
        } else {
            CP_WAIT0();
        }
        __syncthreads();

        const float* As = sm + cs * ASTG;
        const float* Bs = sm + 2 * ASTG + cs * BSTG;

        #pragma unroll
        for (int ks = 0; ks < 4; ks++) {
            const int kk = ks * 8 + lr;
            uint32_t a[2][4];
            #pragma unroll
            for (int mi = 0; mi < 2; mi++) {
                const int r0 = warp_m * 32 + mi * 16 + lq;
                a[mi][0] = __float_as_uint(As[r0 * 36 + kk]);
                a[mi][1] = __float_as_uint(As[(r0 + 8) * 36 + kk]);
                a[mi][2] = __float_as_uint(As[r0 * 36 + kk + 4]);
                a[mi][3] = __float_as_uint(As[(r0 + 8) * 36 + kk + 4]);
            }
            uint32_t b[NT][2];
            #pragma unroll
            for (int ni = 0; ni < NT; ni++) {
                const int n0 = warp_n * (BN / 2) + ni * 8 + lq;
                b[ni][0] = __float_as_uint(Bs[n0 * 36 + kk]);
                b[ni][1] = __float_as_uint(Bs[n0 * 36 + kk + 4]);
            }
            #pragma unroll
            for (int mi = 0; mi < 2; mi++)
                #pragma unroll
                for (int ni = 0; ni < NT; ni++)
                    mma_tf32(acc[mi][ni][0], acc[mi][ni][1], acc[mi][ni][2], acc[mi][ni][3],
                             a[mi][0], a[mi][1], a[mi][2], a[mi][3],
                             b[ni][0], b[ni][1]);
        }
        __syncthreads();
    }

    #pragma unroll
    for (int mi = 0; mi < 2; mi++) {
        const int row0 = bm + warp_m * 32 + mi * 16 + lq;
        float gv0 = 1.f, gv1 = 1.f;
        if (EPI == 2) { gv0 = Gvec[row0]; gv1 = Gvec[row0 + 8]; }
        #pragma unroll
        for (int ni = 0; ni < NT; ni++) {
            const int col = bn + warp_n * (BN / 2) + ni * 8 + lr * 2;
            const size_t i0 = (size_t)row0 * ldc + col;
            const size_t i1 = (size_t)(row0 + 8) * ldc + col;
            float2 o0, o1;
            if (EPI == 0) {
                o0.x = alpha * acc[mi][ni][0]; o0.y = alpha * acc[mi][ni][1];
                o1.x = alpha * acc[mi][ni][2]; o1.y = alpha * acc[mi][ni][3];
                if (ROUND) {
                    o0.x = to_tf32(o0.x); o0.y = to_tf32(o0.y);
                    o1.x = to_tf32(o1.x); o1.y = to_tf32(o1.y);
                }
            } else if (EPI == 1) {
                float2 r0 = *(const float2*)&Res[i0];
                float2 r1 = *(const float2*)&Res[i1];
                o0.x = acc[mi][ni][0] + r0.x; o0.y = acc[mi][ni][1] + r0.y;
                o1.x = acc[mi][ni][2] + r1.x; o1.y = acc[mi][ni][3] + r1.y;
            } else {
                float2 r0 = *(const float2*)&Res[i0];
                float2 r1 = *(const float2*)&Res[i1];
                o0.x = r0.x + acc[mi][ni][0] * gv0; o0.y = r0.y + acc[mi][ni][1] * gv0;
                o1.x = r1.x + acc[mi][ni][2] * gv1; o1.y = r1.y + acc[mi][ni][3] * gv1;
            }
            *(float2*)&C[i0] = o0;
            *(float2*)&C[i1] = o1;
        }
    }
}

// ===========================================================================
// Fused MoE1 + SwiGLU (128-tile, round-5 proven)
// Grid: (FF2/64, NTOK/128, E)
// ===========================================================================
__global__ void __launch_bounds__(256)
moe1_swiglu(const float* __restrict__ hn2, const float* __restrict__ w1t,
            float* __restrict__ act)
{
    constexpr int BN = 128;
    constexpr int NT = 8;
    constexpr int ASTG = 128 * 36;
    constexpr int BSTG = BN * 36;

    extern __shared__ __align__(16) float sm[];
    const uint32_t sbase = smem_u32(sm);
    const int tid = threadIdx.x, wid = tid >> 5, lane = tid & 31;
    const int warp_m = wid & 3, warp_n = wid >> 2;

    const int e    = blockIdx.z;
    const int bn_a = blockIdx.x * 64;
    const int bm   = blockIdx.y * 128;

    const float* A  = hn2 + (size_t)bm * D_;
    const float* Be = w1t + (size_t)e * FF1_ * D_;

    const int nk = D_ / 32;

    auto loadA = [&](int s, int kt) {
        const float* base = A + kt * 32;
        const uint32_t dbase = sbase + (uint32_t)(s * ASTG) * 4;
        #pragma unroll
        for (int i = 0; i < 4; i++) {
            const int c = tid + i * 256;
            const int row = c >> 3, kc = c & 7;
            CP16(dbase + (uint32_t)row * 144 + (uint32_t)kc * 16,
                 base + (size_t)row * D_ + kc * 4);
        }
    };
    auto loadB = [&](int s, int kt) {
        const uint32_t dbase = sbase + (uint32_t)(2 * ASTG + s * BSTG) * 4;
        #pragma unroll
        for (int i = 0; i < 4; i++) {
            const int c = tid + i * 256;
            const int row = c >> 3, kc = c & 7;
            const int half = (row >> 3) & 1;
            const int coll = ((row >> 4) << 3) + (row & 7);
            const int wrow = bn_a + coll + half * FF2_;
            CP16(dbase + (uint32_t)row * 144 + (uint32_t)kc * 16,
                 Be + (size_t)wrow * D_ + kt * 32 + kc * 4);
        }
    };

    float acc[2][NT][4];
    #pragma unroll
    for (int mi = 0; mi < 2; mi++)
        #pragma unroll
        for (int ni = 0; ni < NT; ni++)
            #pragma unroll
            for (int j = 0; j < 4; j++) acc[mi][ni][j] = 0.f;

    loadA(0, 0); loadB(0, 0); CP_COMMIT();

    const int lq = lane >> 2;
    const int lr = lane & 3;

    for (int kt = 0; kt < nk; kt++) {
        const int cs = kt & 1;
        if (kt + 1 < nk) {
            loadA(cs ^ 1, kt + 1); loadB(cs ^ 1, kt + 1); CP_COMMIT();
            CP_WAIT1();
        } else {
            CP_WAIT0();
        }
        __syncthreads();

        const float* As = sm + cs * ASTG;
        const float* Bs = sm + 2 * ASTG + cs * BSTG;

        #pragma unroll
        for (int ks = 0; ks < 4; ks++) {
            const int kk = ks * 8 + lr;
            uint32_t a[2][4];
            #pragma unroll
            for (int mi = 0; mi < 2; mi++) {
                const int r0 = warp_m * 32 + mi * 16 + lq;
                a[mi][0] = __float_as_uint(As[r0 * 36 + kk]);
                a[mi][1] = __float_as_uint(As[(r0 + 8) * 36 + kk]);
                a[mi][2] = __float_as_uint(As[r0 * 36 + kk + 4]);
                a[mi][3] = __float_as_uint(As[(r0 + 8) * 36 + kk + 4]);
            }
            uint32_t b[NT][2];
            #pragma unroll
            for (int ni = 0; ni < NT; ni++) {
                const int n0 = warp_n * 64 + ni * 8 + lq;
                b[ni][0] = __float_as_uint(Bs[n0 * 36 + kk]);
                b[ni][1] = __float_as_uint(Bs[n0 * 36 + kk + 4]);
            }
            #pragma unroll
            for (int mi = 0; mi < 2; mi++)
                #pragma unroll
                for (int ni = 0; ni < NT; ni++)
                    mma_tf32(acc[mi][ni][0], acc[mi][ni][1], acc[mi][ni][2], acc[mi][ni][3],
                             a[mi][0], a[mi][1], a[mi][2], a[mi][3],
                             b[ni][0], b[ni][1]);
        }
        __syncthreads();
    }

    #pragma unroll
    for (int mi = 0; mi < 2; mi++) {
        const int row0 = bm + warp_m * 32 + mi * 16 + lq;
        #pragma unroll
        for (int p = 0; p < 4; p++) {
            const float* av = acc[mi][2 * p];
            const float* bv = acc[mi][2 * p + 1];
            float2 o0, o1;
            o0.x = to_tf32(av[0] * bv[0] / (1.f + __expf(-bv[0])));
            o0.y = to_tf32(av[1] * bv[1] / (1.f + __expf(-bv[1])));
            o1.x = to_tf32(av[2] * bv[2] / (1.f + __expf(-bv[2])));
            o1.y = to_tf32(av[3] * bv[3] / (1.f + __expf(-bv[3])));
            const int col = e * FF2_ + bn_a + warp_n * 32 + p * 8 + lr * 2;
            *(float2*)&act[(size_t)row0 * KMOE2 + col] = o0;
            *(float2*)&act[(size_t)(row0 + 8) * KMOE2 + col] = o1;
        }
    }
}

// ===========================================================================
// Flash attention: fused QK^T + online softmax + PV, one kernel.
// Grid (8 q-blocks, 64 bh). 8 warps; warp w owns 16 q-rows (full kv width).
// Q fragments in registers; K/V tiles via cp.async; P via per-warp smem.
// ===========================================================================
static constexpr int KS_STRIDE = 68;    // floats (272 B/row, 16B aligned)
static constexpr int VS_STRIDE = 132;   // floats (528 B/row)
static constexpr int FA_SMEM =
    (128 * KS_STRIDE + 64 * VS_STRIDE + 128 * VS_STRIDE) * 4;  // 136192 B

__global__ void __launch_bounds__(256)
flash_attn(const float* __restrict__ qkv, const float* __restrict__ vt,
           float* __restrict__ attno)
{
    extern __shared__ __align__(16) float sm[];
    float* Ks = sm;                                   // [128][68]
    float* Vs = sm + 128 * KS_STRIDE;                 // [64][132]
    float* Ps = sm + 128 * KS_STRIDE + 64 * VS_STRIDE;// [128][132]
    const uint32_t sb  = smem_u32(sm);
    const uint32_t KsB = sb;
    const uint32_t VsB = sb + 128 * KS_STRIDE * 4;

    const int tid = threadIdx.x, w = tid >> 5, lane = tid & 31;
    const int lq = lane >> 2, lr = lane & 3;
    const int qb = blockIdx.x;
    const int z  = blockIdx.y;
    const int zb = z >> 4, zh = z & 15;

    const float* Qbase = qkv + (size_t)zb * S_ * 3 * D_ + zh * 64;
    const float* Kbase = Qbase + D_;
    const float* Vt    = vt + (size_t)z * DH_ * S_;

    // ---- Q fragments (rows qb*128 + w*16 + lq, +8; k = 0..63)
    uint32_t qf[8][4];
    {
        const int r0 = qb * 128 + w * 16 + lq;
        const float* q0 = Qbase + (size_t)r0 * 3 * D_;
        const float* q1 = Qbase + (size_t)(r0 + 8) * 3 * D_;
        #pragma unroll
        for (int c = 0; c < 8; c++) {
            qf[c][0] = __float_as_uint(q0[c * 8 + lr]);
            qf[c][1] = __float_as_uint(q1[c * 8 + lr]);
            qf[c][2] = __float_as_uint(q0[c * 8 + lr + 4]);
            qf[c][3] = __float_as_uint(q1[c * 8 + lr + 4]);
        }
    }

    float m0 = -1e30f, m1 = -1e30f, l0 = 0.f, l1 = 0.f;
    float accO[8][4];
    #pragma unroll
    for (int ni = 0; ni < 8; ni++)
        #pragma unroll
        for (int j = 0; j < 4; j++) accO[ni][j] = 0.f;

    const int rowA = w * 16 + lq;

    for (int j = 0; j < 8; j++) {
        __syncthreads();                      // prior-iter Ks/Vs reads done
        // ---- load K tile (128 kv x 64 dh)
        #pragma unroll
        for (int i = 0; i < 8; i++) {
            const int c = tid + i * 256;
            const int row = c >> 4, kc = c & 15;
            CP16(KsB + (uint32_t)row * (KS_STRIDE * 4) + (uint32_t)kc * 16,
                 Kbase + (size_t)(j * 128 + row) * 3 * D_ + kc * 4);
        }
        // ---- load V tile (64 dh x 128 kv) from vt
        #pragma unroll
        for (int i = 0; i < 8; i++) {
            const int c = tid + i * 256;
            const int row = c >> 5, kc = c & 31;
            CP16(VsB + (uint32_t)row * (VS_STRIDE * 4) + (uint32_t)kc * 16,
                 Vt + (size_t)row * S_ + j * 128 + kc * 4);
        }
        CP_COMMIT(); CP_WAIT0();
        __syncthreads();

        // ---- S = (Q K^T) * 0.125
        float s[16][4];
        #pragma unroll
        for (int ni = 0; ni < 16; ni++)
            #pragma unroll
            for (int jj = 0; jj < 4; jj++) s[ni][jj] = 0.f;

        #pragma unroll
        for (int c = 0; c < 8; c++) {
            const int kk = c * 8 + lr;
            #pragma unroll
            for (int ni = 0; ni < 16; ni++) {
                const int n0 = ni * 8 + lq;
                const uint32_t b0 = __float_as_uint(Ks[n0 * KS_STRIDE + kk]);
                const uint32_t b1 = __float_as_uint(Ks[n0 * KS_STRIDE + kk + 4]);
                mma_tf32(s[ni][0], s[ni][1], s[ni][2], s[ni][3],
                         qf[c][0], qf[c][1], qf[c][2], qf[c][3], b0, b1);
            }
        }

        // ---- online softmax (rows lq -> c0,c1 ; lq+8 -> c2,c3)
        float rm0 = -1e30f, rm1 = -1e30f;
        #pragma unroll
        for (int ni = 0; ni < 16; ni++) {
            s[ni][0] *= 0.125f; s[ni][1] *= 0.125f;
            s[ni][2] *= 0.125f; s[ni][3] *= 0.125f;
            rm0 = fmaxf(rm0, fmaxf(s[ni][0], s[ni][1]));
            rm1 = fmaxf(rm1, fmaxf(s[ni][2], s[ni][3]));
        }
        rm0 = fmaxf(rm0, __shfl_xor_sync(~0u, rm0, 1));
        rm0 = fmaxf(rm0, __shfl_xor_sync(~0u, rm0, 2));
        rm1 = fmaxf(rm1, __shfl_xor_sync(~0u, rm1, 1));
        rm1 = fmaxf(rm1, __shfl_xor_sync(~0u, rm1, 2));

        const float mn0 = fmaxf(m0, rm0), mn1 = fmaxf(m1, rm1);
        const float corr0 = __expf(m0 - mn0), corr1 = __expf(m1 - mn1);
        m0 = mn0; m1 = mn1;

        float ps0 = 0.f, ps1 = 0.f;
        #pragma unroll
        for (int ni = 0; ni < 16; ni++) {
            s[ni][0] = __expf(s[ni][0] - m0); ps0 += s[ni][0];
            s[ni][1] = __expf(s[ni][1] - m0); ps0 += s[ni][1];
            s[ni][2] = __expf(s[ni][2] - m1); ps1 += s[ni][2];
            s[ni][3] = __expf(s[ni][3] - m1); ps1 += s[ni][3];
        }
        ps0 += __shfl_xor_sync(~0u, ps0, 1); ps0 += __shfl_xor_sync(~0u, ps0, 2);
        ps1 += __shfl_xor_sync(~0u, ps1, 1); ps1 += __shfl_xor_sync(~0u, ps1, 2);
        l0 = l0 * corr0 + ps0;
        l1 = l1 * corr1 + ps1;

        #pragma unroll
        for (int ni = 0; ni < 8; ni++) {
            accO[ni][0] *= corr0; accO[ni][1] *= corr0;
            accO[ni][2] *= corr1; accO[ni][3] *= corr1;
        }

        // ---- P (tf32) -> smem (warp-private rows)
        #pragma unroll
        for (int ni = 0; ni < 16; ni++) {
            const int col = ni * 8 + lr * 2;
            Ps[rowA * VS_STRIDE + col]           = to_tf32(s[ni][0]);
            Ps[rowA * VS_STRIDE + col + 1]       = to_tf32(s[ni][1]);
            Ps[(rowA + 8) * VS_STRIDE + col]     = to_tf32(s[ni][2]);
            Ps[(rowA + 8) * VS_STRIDE + col + 1] = to_tf32(s[ni][3]);
        }
        __syncwarp();

        // ---- O += P V  (K = 128 -> 16 chunks)
        #pragma unroll
        for (int c2 = 0; c2 < 16; c2++) {
            const int kk = c2 * 8 + lr;
            const uint32_t a0 = __float_as_uint(Ps[rowA * VS_STRIDE + kk]);
            const uint32_t a1 = __float_as_uint(Ps[(rowA + 8) * VS_STRIDE + kk]);
            const uint32_t a2 = __float_as_uint(Ps[rowA * VS_STRIDE + kk + 4]);
            const uint32_t a3 = __float_as_uint(Ps[(rowA + 8) * VS_STRIDE + kk + 4]);
            #pragma unroll
            for (int ni = 0; ni < 8; ni++) {
                const int n0 = ni * 8 + lq;
                const uint32_t b0 = __float_as_uint(Vs[n0 * VS_STRIDE + kk]);
                const uint32_t b1 = __float_as_uint(Vs[n0 * VS_STRIDE + kk + 4]);
                mma_tf32(accO[ni][0], accO[ni][1], accO[ni][2], accO[ni][3],
                         a0, a1, a2, a3, b0, b1);
            }
        }
    }

    // ---- epilogue
    const float il0 = 1.f / l0, il1 = 1.f / l1;
    const int r0 = zb * S_ + qb * 128 + w * 16 + lq;
    #pragma unroll
    for (int ni = 0; ni < 8; ni++) {
        const int col = zh * 64 + ni * 8 + lr * 2;
        float2 o0, o1;
        o0.x = to_tf32(accO[ni][0] * il0); o0.y = to_tf32(accO[ni][1] * il0);
        o1.x = to_tf32(accO[ni][2] * il1); o1.y = to_tf32(accO[ni][3] * il1);
        *(float2*)&attno[(size_t)r0 * D_ + col] = o0;
        *(float2*)&attno[(size_t)(r0 + 8) * D_ + col] = o1;
    }
}

// ===========================================================================
// RMSNorm (rounds output to tf32)
// ===========================================================================
__global__ void rmsnorm_k(const float* __restrict__ x, const float* __restrict__ w,
                          float* __restrict__ y, float eps)
{
    const int row = blockIdx.x;
    const float* xr = x + (size_t)row * D_;
    float v[4];
    float s = 0.f;
    #pragma unroll
    for (int i = 0; i < 4; i++) { v[i] = xr[threadIdx.x + 256 * i]; s += v[i] * v[i]; }
    #pragma unroll
    for (int o = 16; o > 0; o >>= 1) s += __shfl_xor_sync(~0u, s, o);
    __shared__ float red[8];
    if ((threadIdx.x & 31) == 0) red[threadIdx.x >> 5] = s;
    __syncthreads();
    if (threadIdx.x < 8) {
        float t = red[threadIdx.x];
        #pragma unroll
        for (int o = 4; o > 0; o >>= 1) t += __shfl_xor_sync(0xffu, t, o);
        if (threadIdx.x == 0) red[0] = t;
    }
    __syncthreads();
    const float inv = rsqrtf(red[0] / (float)D_ + eps);
    float* yr = y + (size_t)row * D_;
    #pragma unroll
    for (int i = 0; i < 4; i++)
        yr[threadIdx.x + 256 * i] = to_tf32(v[i] * inv * w[threadIdx.x + 256 * i]);
}

// ===========================================================================
// Gating — from raw fp32 h2
// ===========================================================================
__global__ void gate_k(const float* __restrict__ h2, const float* __restrict__ n2w,
                       const float* __restrict__ gw,
                       const float* __restrict__ gb, const float* __restrict__ grw,
                       float* __restrict__ g)
{
    const int n    = blockIdx.x * 4 + (threadIdx.x >> 5);
    const int lane = threadIdx.x & 31;
    const float* xr = h2 + (size_t)n * D_;
    float acc[E_];
    float ssx = 0.f;
    #pragma unroll
    for (int e = 0; e < E_; e++) acc[e] = 0.f;
    for (int d = lane; d < D_; d += 32) {
        const float xv = xr[d];
        ssx += xv * xv;
        const float xw = xv * n2w[d];
        #pragma unroll
        for (int e = 0; e < E_; e++) acc[e] += xw * gw[e * D_ + d];
    }
    #pragma unroll
    for (int o = 16; o > 0; o >>= 1) ssx += __shfl_xor_sync(~0u, ssx, o);
    #pragma unroll
    for (int e = 0; e < E_; e++)
        #pragma unroll
        for (int o = 16; o > 0; o >>= 1) acc[e] += __shfl_xor_sync(~0u, acc[e], o);
    if (lane == 0) {
        const float invr = rsqrtf(ssx / (float)D_ + 1e-8f);
        float l[E_], ss = 0.f;
        #pragma unroll
        for (int e = 0; e < E_; e++) { l[e] = acc[e] * invr + gb[e]; ss += l[e] * l[e]; }
        const float inv = rsqrtf(ss / (float)E_ + 1.1920929e-7f);
        float m = -INFINITY;
        #pragma unroll
        for (int e = 0; e < E_; e++) { l[e] = l[e] * inv * grw[e] * 2.0f; m = fmaxf(m, l[e]); }
        float sum = 0.f, mx = 0.f;
        #pragma unroll
        for (int e = 0; e < E_; e++) {
            const float ex = __expf(l[e] - m);
            sum += ex; mx = fmaxf(mx, ex);
        }
        const float top = mx / sum;
        g[n] = top / (top + 1e-6f);
    }
}

// ===========================================================================
// Batched transpose: out[z][c][r] = tf32(in[z][r][c])
// ===========================================================================
__global__ void transpose_k(const float* __restrict__ in, float* __restrict__ out,
                            int ldin, int ldout,
                            int zDiv, long zi1, long zi2, long zo1, long zo2)
{
    __shared__ float t[32][33];
    const int z = blockIdx.z;
    const int zb = z / zDiv, zh = z - zb * zDiv;
    in  += (size_t)zb * zi1 + (size_t)zh * zi2;
    out += (size_t)zb * zo1 + (size_t)zh * zo2;
    const int c0 = blockIdx.x * 32, r0 = blockIdx.y * 32;
    #pragma unroll
    for (int i = 0; i < 4; i++)
        t[threadIdx.y + i * 8][threadIdx.x] =
            in[(size_t)(r0 + threadIdx.y + i * 8) * ldin + c0 + threadIdx.x];
    __syncthreads();
    #pragma unroll
    for (int i = 0; i < 4; i++)
        out[(size_t)(c0 + threadIdx.y + i * 8) * ldout + r0 + threadIdx.x] =
            to_tf32(t[threadIdx.x][threadIdx.y + i * 8]);
}

// ===========================================================================
// Round-copy to tf32
// ===========================================================================
__global__ void roundcpy_k(const float* __restrict__ in, float* __restrict__ out, int n)
{
    for (int i = blockIdx.x * blockDim.x + threadIdx.x; i < n; i += gridDim.x * blockDim.x)
        out[i] = to_tf32(in[i]);
}

// ===========================================================================
// Launch
// ===========================================================================
static inline int smem_bytes(int bn) { return (2 * 128 * 36 + 2 * bn * 36) * 4; }

extern "C" void kernel_launch(void* const* d_in, const int* in_sizes, int n_in,
                              void* d_out, int out_size)
{
    const float* x      = (const float*)d_in[0];
    const float* w_qkv  = (const float*)d_in[1];
    const float* w_out  = (const float*)d_in[2];
    const float* norm1w = (const float*)d_in[3];
    const float* norm2w = (const float*)d_in[4];
    const float* gate_w = (const float*)d_in[5];
    const float* gate_b = (const float*)d_in[6];
    const float* gate_rw= (const float*)d_in[7];
    const float* w1     = (const float*)d_in[8];
    const float* w2     = (const float*)d_in[9];
    float* out = (float*)d_out;

    float *hn1, *wqkvr, *woutr, *qkv, *vt, *attno, *h2, *hn2, *gate, *w1t, *w2t, *act;
    cudaGetSymbolAddress((void**)&hn1,    g_hn1);
    cudaGetSymbolAddress((void**)&wqkvr,  g_wqkvr);
    cudaGetSymbolAddress((void**)&woutr,  g_woutr);
    cudaGetSymbolAddress((void**)&qkv,    g_qkv);
    cudaGetSymbolAddress((void**)&vt,     g_vt);
    cudaGetSymbolAddress((void**)&attno,  g_attno);
    cudaGetSymbolAddress((void**)&h2,     g_h2);
    cudaGetSymbolAddress((void**)&hn2,    g_hn2);
    cudaGetSymbolAddress((void**)&gate,   g_gate);
    cudaGetSymbolAddress((void**)&w1t,    g_w1t);
    cudaGetSymbolAddress((void**)&w2t,    g_w2t);
    cudaGetSymbolAddress((void**)&act,    g_act);

    cudaFuncSetAttribute(mma_gemm<0,128,true >, cudaFuncAttributeMaxDynamicSharedMemorySize, smem_bytes(128));
    cudaFuncSetAttribute(mma_gemm<1,128,false>, cudaFuncAttributeMaxDynamicSharedMemorySize, smem_bytes(128));
    cudaFuncSetAttribute(mma_gemm<2,128,false>, cudaFuncAttributeMaxDynamicSharedMemorySize, smem_bytes(128));
    cudaFuncSetAttribute(moe1_swiglu,           cudaFuncAttributeMaxDynamicSharedMemorySize, smem_bytes(128));
    cudaFuncSetAttribute(flash_attn,            cudaFuncAttributeMaxDynamicSharedMemorySize, FA_SMEM);

    // --- weight prep ---
    roundcpy_k<<<2048, 256>>>(w_qkv, wqkvr, 3 * D_ * D_);
    roundcpy_k<<<1024, 256>>>(w_out, woutr, D_ * D_);
    transpose_k<<<dim3(FF1_ / 32, D_ / 32, E_), dim3(32, 8)>>>(
        w1, w1t, FF1_, D_, 1, (long)D_ * FF1_, 0, (long)D_ * FF1_, 0);
    transpose_k<<<dim3(D_ / 32, KMOE2 / 32, 1), dim3(32, 8)>>>(
        w2, w2t, D_, KMOE2, 1, 0, 0, 0, 0);

    // --- 1) rmsnorm1 ---
    rmsnorm_k<<<NTOK, 256>>>(x, norm1w, hn1, 1e-8f);

    // --- 2) QKV ---
    mma_gemm<0,128,true><<<dim3(3 * D_ / 128, NTOK / 128, 1), 256, smem_bytes(128)>>>(
        hn1, wqkvr, qkv, nullptr, nullptr,
        NTOK, 3 * D_, D_, D_, D_, 3 * D_,
        1, 0, 0, 0, 0, 0, 0, 1.f);

    // --- 3) V transpose ---
    transpose_k<<<dim3(DH_ / 32, S_ / 32, B_ * H_), dim3(32, 8)>>>(
        qkv + 2 * D_, vt, 3 * D_, S_,
        H_, (long)S_ * 3 * D_, (long)DH_,
        (long)H_ * DH_ * S_, (long)DH_ * S_);

    // --- 4-6) fused flash attention ---
    flash_attn<<<dim3(S_ / 128, B_ * H_), 256, FA_SMEM>>>(qkv, vt, attno);

    // --- 7) h2 = x + O w_out^T ---
    mma_gemm<1,128,false><<<dim3(D_ / 128, NTOK / 128, 1), 256, smem_bytes(128)>>>(
        attno, woutr, h2, x, nullptr,
        NTOK, D_, D_, D_, D_, D_,
        1, 0, 0, 0, 0, 0, 0, 1.f);

    // --- 8) rmsnorm2 + gate ---
    rmsnorm_k<<<NTOK, 256>>>(h2, norm2w, hn2, 1e-8f);
    gate_k<<<NTOK / 4, 128>>>(h2, norm2w, gate_w, gate_b, gate_rw, gate);

    // --- 9+10) fused MoE1 + SwiGLU -> act [4096, 16384] ---
    moe1_swiglu<<<dim3(FF2_ / 64, NTOK / 128, E_), 256, smem_bytes(128)>>>(
        hn2, w1t, act);

    // --- 11) MoE2: out = h2 + (act x w2t^T) * g[n] ---
    mma_gemm<2,128,false><<<dim3(D_ / 128, NTOK / 128, 1), 256, smem_bytes(128)>>>(
        act, w2t, out, h2, gate,
        NTOK, D_, KMOE2, KMOE2, KMOE2, D_,
        1, 0, 0, 0, 0, 0, 0, 1.f);

    (void)in_sizes; (void)n_in; (void)out_size;
}

// round 8
// speedup vs baseline: 1.6844x; 1.5784x over previous
#include <cuda_runtime.h>
#include <cuda_fp16.h>
#include <cstdint>
#include <cmath>

// ===========================================================================
// Problem constants
// ===========================================================================
static constexpr int B_   = 4;
static constexpr int S_   = 1024;
static constexpr int D_   = 1024;
static constexpr int H_   = 16;
static constexpr int DH_  = 64;
static constexpr int E_   = 8;
static constexpr int FF1_ = 4096;
static constexpr int FF2_ = 2048;
static constexpr int NTOK = B_ * S_;        // 4096
static constexpr int KMOE2 = E_ * FF2_;     // 16384

// ===========================================================================
// Scratch
// ===========================================================================
__device__ __half g_hn1  [(size_t)NTOK * D_];
__device__ __half g_wqkvr[(size_t)3 * D_ * D_];
__device__ __half g_woutr[(size_t)D_ * D_];
__device__ __half g_qkv  [(size_t)NTOK * 3 * D_];
__device__ __half g_vt   [(size_t)B_ * H_ * DH_ * S_];
__device__ __half g_attno[(size_t)NTOK * D_];
__device__ float  g_h2   [(size_t)NTOK * D_];
__device__ __half g_hn2  [(size_t)NTOK * D_];
__device__ float  g_gate [NTOK];
__device__ __half g_w1t  [(size_t)E_ * FF1_ * D_];
__device__ __half g_w2t  [(size_t)D_ * KMOE2];
__device__ __half g_act  [(size_t)NTOK * KMOE2];

// ===========================================================================
// Helpers
// ===========================================================================
__device__ __forceinline__ uint32_t smem_u32(const void* p) {
    uint32_t a;
    asm("{ .reg .u64 t; cvta.to.shared.u64 t, %1; cvt.u32.u64 %0, t; }" : "=r"(a) : "l"(p));
    return a;
}

#define CP16(dst, src) \
    asm volatile("cp.async.cg.shared.global [%0], [%1], 16;" :: "r"(dst), "l"(src))
#define CP_COMMIT()  asm volatile("cp.async.commit_group;" ::: "memory")
#define CP_WAIT1()   asm volatile("cp.async.wait_group 1;" ::: "memory")
#define CP_WAIT0()   asm volatile("cp.async.wait_group 0;" ::: "memory")

__device__ __forceinline__ void mma_f16(float& c0, float& c1, float& c2, float& c3,
                                        uint32_t a0, uint32_t a1, uint32_t a2, uint32_t a3,
                                        uint32_t b0, uint32_t b1)
{
    asm volatile(
        "mma.sync.aligned.m16n8k16.row.col.f32.f16.f16.f32 "
        "{%0,%1,%2,%3}, {%4,%5,%6,%7}, {%8,%9}, {%0,%1,%2,%3};"
        : "+f"(c0), "+f"(c1), "+f"(c2), "+f"(c3)
        : "r"(a0), "r"(a1), "r"(a2), "r"(a3), "r"(b0), "r"(b1));
}

// ===========================================================================
// fp16 NT GEMM: C[M,N] = A[M,K](half,K-major) * B[N,K](half,K-major)^T
//   EPI 0: C(half) = acc            EPI 1: C(float) = acc + Res
//   EPI 2: C(float) = Res + acc * Gvec[row]
// Block 128x128x32(halves); 8 warps (4m x 2n); warp tile 32x64; m16n8k16.
// SMEM rows padded to 40 halves (80 B = 20 banks -> conflict-free frags).
// ===========================================================================
template<int EPI>
__global__ void __launch_bounds__(256)
gemm_f16(const __half* __restrict__ A, const __half* __restrict__ B,
         void* __restrict__ Cv, const float* __restrict__ Res,
         const float* __restrict__ Gvec,
         int M, int N, int K, int lda, int ldb, int ldc)
{
    constexpr int ASTG = 128 * 40;   // halves per stage
    constexpr int BSTG = 128 * 40;

    extern __shared__ __align__(16) __half smh[];
    const uint32_t sbase = smem_u32(smh);
    const int tid = threadIdx.x, wid = tid >> 5, lane = tid & 31;
    const int warp_m = wid & 3, warp_n = wid >> 2;

    const int bm = blockIdx.y * 128;
    const int bn = blockIdx.x * 128;
    A += (size_t)bm * lda;
    B += (size_t)bn * ldb;

    const int nk = K / 32;

    auto loadA = [&](int s, int kt) {
        const __half* base = A + kt * 32;
        const uint32_t dbase = sbase + (uint32_t)(s * ASTG) * 2;
        #pragma unroll
        for (int i = 0; i < 2; i++) {
            const int c = tid + i * 256;      // 0..511
            const int row = c >> 2, kc = c & 3;
            CP16(dbase + (uint32_t)row * 80 + (uint32_t)kc * 16,
                 base + (size_t)row * lda + kc * 8);
        }
    };
    auto loadB = [&](int s, int kt) {
        const __half* base = B + kt * 32;
        const uint32_t dbase = sbase + (uint32_t)(2 * ASTG + s * BSTG) * 2;
        #pragma unroll
        for (int i = 0; i < 2; i++) {
            const int c = tid + i * 256;
            const int row = c >> 2, kc = c & 3;
            CP16(dbase + (uint32_t)row * 80 + (uint32_t)kc * 16,
                 base + (size_t)row * ldb + kc * 8);
        }
    };

    float acc[2][8][4];
    #pragma unroll
    for (int mi = 0; mi < 2; mi++)
        #pragma unroll
        for (int ni = 0; ni < 8; ni++)
            #pragma unroll
            for (int j = 0; j < 4; j++) acc[mi][ni][j] = 0.f;

    loadA(0, 0); loadB(0, 0); CP_COMMIT();

    const int lq = lane >> 2;
    const int lr = lane & 3;

    for (int kt = 0; kt < nk; kt++) {
        const int cs = kt & 1;
        if (kt + 1 < nk) {
            loadA(cs ^ 1, kt + 1); loadB(cs ^ 1, kt + 1); CP_COMMIT();
            CP_WAIT1();
        } else {
            CP_WAIT0();
        }
        __syncthreads();

        const __half* As = smh + cs * ASTG;
        const __half* Bs = smh + 2 * ASTG + cs * BSTG;

        #pragma unroll
        for (int ks = 0; ks < 2; ks++) {
            const int kb = ks * 16 + 2 * lr;
            uint32_t a[2][4];
            #pragma unroll
            for (int mi = 0; mi < 2; mi++) {
                const int r0 = warp_m * 32 + mi * 16 + lq;
                a[mi][0] = *(const uint32_t*)&As[r0 * 40 + kb];
                a[mi][1] = *(const uint32_t*)&As[(r0 + 8) * 40 + kb];
                a[mi][2] = *(const uint32_t*)&As[r0 * 40 + kb + 8];
                a[mi][3] = *(const uint32_t*)&As[(r0 + 8) * 40 + kb + 8];
            }
            uint32_t b[8][2];
            #pragma unroll
            for (int ni = 0; ni < 8; ni++) {
                const int n0 = warp_n * 64 + ni * 8 + lq;
                b[ni][0] = *(const uint32_t*)&Bs[n0 * 40 + kb];
                b[ni][1] = *(const uint32_t*)&Bs[n0 * 40 + kb + 8];
            }
            #pragma unroll
            for (int mi = 0; mi < 2; mi++)
                #pragma unroll
                for (int ni = 0; ni < 8; ni++)
                    mma_f16(acc[mi][ni][0], acc[mi][ni][1], acc[mi][ni][2], acc[mi][ni][3],
                            a[mi][0], a[mi][1], a[mi][2], a[mi][3],
                            b[ni][0], b[ni][1]);
        }
        __syncthreads();
    }

    #pragma unroll
    for (int mi = 0; mi < 2; mi++) {
        const int row0 = bm + warp_m * 32 + mi * 16 + lq;
        float gv0 = 1.f, gv1 = 1.f;
        if (EPI == 2) { gv0 = Gvec[row0]; gv1 = Gvec[row0 + 8]; }
        #pragma unroll
        for (int ni = 0; ni < 8; ni++) {
            const int col = bn + warp_n * 64 + ni * 8 + lr * 2;
            const size_t i0 = (size_t)row0 * ldc + col;
            const size_t i1 = (size_t)(row0 + 8) * ldc + col;
            if (EPI == 0) {
                __half* C = (__half*)Cv;
                *(__half2*)&C[i0] = __floats2half2_rn(acc[mi][ni][0], acc[mi][ni][1]);
                *(__half2*)&C[i1] = __floats2half2_rn(acc[mi][ni][2], acc[mi][ni][3]);
            } else if (EPI == 1) {
                float* C = (float*)Cv;
                float2 r0 = *(const float2*)&Res[i0];
                float2 r1 = *(const float2*)&Res[i1];
                float2 o0 = {acc[mi][ni][0] + r0.x, acc[mi][ni][1] + r0.y};
                float2 o1 = {acc[mi][ni][2] + r1.x, acc[mi][ni][3] + r1.y};
                *(float2*)&C[i0] = o0;
                *(float2*)&C[i1] = o1;
            } else {
                float* C = (float*)Cv;
                float2 r0 = *(const float2*)&Res[i0];
                float2 r1 = *(const float2*)&Res[i1];
                float2 o0 = {r0.x + acc[mi][ni][0] * gv0, r0.y + acc[mi][ni][1] * gv0};
                float2 o1 = {r1.x + acc[mi][ni][2] * gv1, r1.y + acc[mi][ni][3] * gv1};
                *(float2*)&C[i0] = o0;
                *(float2*)&C[i1] = o1;
            }
        }
    }
}

// ===========================================================================
// Fused MoE1 + SwiGLU (fp16): 128 tokens x 64 act-cols per CTA.
// B tile interleaves a/b halves by 8-row groups (even ni = a, odd ni = b).
// Grid: (FF2/64, NTOK/128, E)
// ===========================================================================
__global__ void __launch_bounds__(256)
moe1_swiglu_f16(const __half* __restrict__ hn2, const __half* __restrict__ w1t,
                __half* __restrict__ act)
{
    constexpr int ASTG = 128 * 40;
    constexpr int BSTG = 128 * 40;

    extern __shared__ __align__(16) __half smh[];
    const uint32_t sbase = smem_u32(smh);
    const int tid = threadIdx.x, wid = tid >> 5, lane = tid & 31;
    const int warp_m = wid & 3, warp_n = wid >> 2;

    const int e    = blockIdx.z;
    const int bn_a = blockIdx.x * 64;
    const int bm   = blockIdx.y * 128;

    const __half* A  = hn2 + (size_t)bm * D_;
    const __half* Be = w1t + (size_t)e * FF1_ * D_;

    const int nk = D_ / 32;

    auto loadA = [&](int s, int kt) {
        const __half* base = A + kt * 32;
        const uint32_t dbase = sbase + (uint32_t)(s * ASTG) * 2;
        #pragma unroll
        for (int i = 0; i < 2; i++) {
            const int c = tid + i * 256;
            const int row = c >> 2, kc = c & 3;
            CP16(dbase + (uint32_t)row * 80 + (uint32_t)kc * 16,
                 base + (size_t)row * D_ + kc * 8);
        }
    };
    auto loadB = [&](int s, int kt) {
        const uint32_t dbase = sbase + (uint32_t)(2 * ASTG + s * BSTG) * 2;
        #pragma unroll
        for (int i = 0; i < 2; i++) {
            const int c = tid + i * 256;
            const int row = c >> 2, kc = c & 3;
            const int half_ = (row >> 3) & 1;
            const int coll = ((row >> 4) << 3) + (row & 7);
            const int wrow = bn_a + coll + half_ * FF2_;
            CP16(dbase + (uint32_t)row * 80 + (uint32_t)kc * 16,
                 Be + (size_t)wrow * D_ + kt * 32 + kc * 8);
        }
    };

    float acc[2][8][4];
    #pragma unroll
    for (int mi = 0; mi < 2; mi++)
        #pragma unroll
        for (int ni = 0; ni < 8; ni++)
            #pragma unroll
            for (int j = 0; j < 4; j++) acc[mi][ni][j] = 0.f;

    loadA(0, 0); loadB(0, 0); CP_COMMIT();

    const int lq = lane >> 2;
    const int lr = lane & 3;

    for (int kt = 0; kt < nk; kt++) {
        const int cs = kt & 1;
        if (kt + 1 < nk) {
            loadA(cs ^ 1, kt + 1); loadB(cs ^ 1, kt + 1); CP_COMMIT();
            CP_WAIT1();
        } else {
            CP_WAIT0();
        }
        __syncthreads();

        const __half* As = smh + cs * ASTG;
        const __half* Bs = smh + 2 * ASTG + cs * BSTG;

        #pragma unroll
        for (int ks = 0; ks < 2; ks++) {
            const int kb = ks * 16 + 2 * lr;
            uint32_t a[2][4];
            #pragma unroll
            for (int mi = 0; mi < 2; mi++) {
                const int r0 = warp_m * 32 + mi * 16 + lq;
                a[mi][0] = *(const uint32_t*)&As[r0 * 40 + kb];
                a[mi][1] = *(const uint32_t*)&As[(r0 + 8) * 40 + kb];
                a[mi][2] = *(const uint32_t*)&As[r0 * 40 + kb + 8];
                a[mi][3] = *(const uint32_t*)&As[(r0 + 8) * 40 + kb + 8];
            }
            uint32_t b[8][2];
            #pragma unroll
            for (int ni = 0; ni < 8; ni++) {
                const int n0 = warp_n * 64 + ni * 8 + lq;
                b[ni][0] = *(const uint32_t*)&Bs[n0 * 40 + kb];
                b[ni][1] = *(const uint32_t*)&Bs[n0 * 40 + kb + 8];
            }
            #pragma unroll
            for (int mi = 0; mi < 2; mi++)
                #pragma unroll
                for (int ni = 0; ni < 8; ni++)
                    mma_f16(acc[mi][ni][0], acc[mi][ni][1], acc[mi][ni][2], acc[mi][ni][3],
                            a[mi][0], a[mi][1], a[mi][2], a[mi][3],
                            b[ni][0], b[ni][1]);
        }
        __syncthreads();
    }

    #pragma unroll
    for (int mi = 0; mi < 2; mi++) {
        const int row0 = bm + warp_m * 32 + mi * 16 + lq;
        #pragma unroll
        for (int p = 0; p < 4; p++) {
            const float* av = acc[mi][2 * p];
            const float* bv = acc[mi][2 * p + 1];
            const float v0 = av[0] * bv[0] / (1.f + __expf(-bv[0]));
            const float v1 = av[1] * bv[1] / (1.f + __expf(-bv[1]));
            const float v2 = av[2] * bv[2] / (1.f + __expf(-bv[2]));
            const float v3 = av[3] * bv[3] / (1.f + __expf(-bv[3]));
            const int col = e * FF2_ + bn_a + warp_n * 32 + p * 8 + lr * 2;
            *(__half2*)&act[(size_t)row0 * KMOE2 + col] = __floats2half2_rn(v0, v1);
            *(__half2*)&act[(size_t)(row0 + 8) * KMOE2 + col] = __floats2half2_rn(v2, v3);
        }
    }
}

// ===========================================================================
// Flash attention fp16: fused QK^T + online softmax + PV.
// Grid (8 q-blocks, 64 bh). 8 warps; warp owns 16 q-rows x full 128-kv tile.
// ===========================================================================
static constexpr int KSH = 72;    // K smem stride (halves): 144 B
static constexpr int VSH = 136;   // V/P smem stride (halves): 272 B
static constexpr int FA_SMEM = (128 * KSH + 64 * VSH + 128 * VSH) * 2;  // 70656 B

__global__ void __launch_bounds__(256)
flash_attn_f16(const __half* __restrict__ qkv, const __half* __restrict__ vt,
               __half* __restrict__ attno)
{
    extern __shared__ __align__(16) __half smh[];
    __half* Ks = smh;
    __half* Vs = smh + 128 * KSH;
    __half* Ps = smh + 128 * KSH + 64 * VSH;
    const uint32_t sb  = smem_u32(smh);
    const uint32_t KsB = sb;
    const uint32_t VsB = sb + 128 * KSH * 2;

    const int tid = threadIdx.x, w = tid >> 5, lane = tid & 31;
    const int lq = lane >> 2, lr = lane & 3;
    const int qb = blockIdx.x;
    const int z  = blockIdx.y;
    const int zb = z >> 4, zh = z & 15;

    const __half* Qbase = qkv + (size_t)zb * S_ * 3 * D_ + zh * 64;
    const __half* Kbase = Qbase + D_;
    const __half* Vt    = vt + (size_t)z * DH_ * S_;

    // ---- Q fragments in registers (4 k-steps of 16 over dh=64)
    uint32_t qf[4][4];
    {
        const int r0 = qb * 128 + w * 16 + lq;
        const __half* q0 = Qbase + (size_t)r0 * 3 * D_;
        const __half* q1 = Qbase + (size_t)(r0 + 8) * 3 * D_;
        #pragma unroll
        for (int c = 0; c < 4; c++) {
            qf[c][0] = *(const uint32_t*)&q0[c * 16 + 2 * lr];
            qf[c][1] = *(const uint32_t*)&q1[c * 16 + 2 * lr];
            qf[c][2] = *(const uint32_t*)&q0[c * 16 + 2 * lr + 8];
            qf[c][3] = *(const uint32_t*)&q1[c * 16 + 2 * lr + 8];
        }
    }

    float m0 = -1e30f, m1 = -1e30f, l0 = 0.f, l1 = 0.f;
    float accO[8][4];
    #pragma unroll
    for (int ni = 0; ni < 8; ni++)
        #pragma unroll
        for (int j = 0; j < 4; j++) accO[ni][j] = 0.f;

    const int rowA = w * 16 + lq;

    for (int j = 0; j < 8; j++) {
        __syncthreads();
        // ---- K tile: 128 kv x 64 dh (halves), 8 chunks/row
        #pragma unroll
        for (int i = 0; i < 4; i++) {
            const int c = tid + i * 256;
            const int row = c >> 3, kc = c & 7;
            CP16(KsB + (uint32_t)row * (KSH * 2) + (uint32_t)kc * 16,
                 Kbase + (size_t)(j * 128 + row) * 3 * D_ + kc * 8);
        }
        // ---- V tile: 64 dh x 128 kv (halves), 16 chunks/row
        #pragma unroll
        for (int i = 0; i < 4; i++) {
            const int c = tid + i * 256;
            const int row = c >> 4, kc = c & 15;
            CP16(VsB + (uint32_t)row * (VSH * 2) + (uint32_t)kc * 16,
                 Vt + (size_t)row * S_ + j * 128 + kc * 8);
        }
        CP_COMMIT(); CP_WAIT0();
        __syncthreads();

        // ---- S = (Q K^T) * 0.125
        float s[16][4];
        #pragma unroll
        for (int ni = 0; ni < 16; ni++)
            #pragma unroll
            for (int jj = 0; jj < 4; jj++) s[ni][jj] = 0.f;

        #pragma unroll
        for (int c = 0; c < 4; c++) {
            const int kb = c * 16 + 2 * lr;
            #pragma unroll
            for (int ni = 0; ni < 16; ni++) {
                const int n0 = ni * 8 + lq;
                const uint32_t b0 = *(const uint32_t*)&Ks[n0 * KSH + kb];
                const uint32_t b1 = *(const uint32_t*)&Ks[n0 * KSH + kb + 8];
                mma_f16(s[ni][0], s[ni][1], s[ni][2], s[ni][3],
                        qf[c][0], qf[c][1], qf[c][2], qf[c][3], b0, b1);
            }
        }

        // ---- online softmax
        float rm0 = -1e30f, rm1 = -1e30f;
        #pragma unroll
        for (int ni = 0; ni < 16; ni++) {
            s[ni][0] *= 0.125f; s[ni][1] *= 0.125f;
            s[ni][2] *= 0.125f; s[ni][3] *= 0.125f;
            rm0 = fmaxf(rm0, fmaxf(s[ni][0], s[ni][1]));
            rm1 = fmaxf(rm1, fmaxf(s[ni][2], s[ni][3]));
        }
        rm0 = fmaxf(rm0, __shfl_xor_sync(~0u, rm0, 1));
        rm0 = fmaxf(rm0, __shfl_xor_sync(~0u, rm0, 2));
        rm1 = fmaxf(rm1, __shfl_xor_sync(~0u, rm1, 1));
        rm1 = fmaxf(rm1, __shfl_xor_sync(~0u, rm1, 2));

        const float mn0 = fmaxf(m0, rm0), mn1 = fmaxf(m1, rm1);
        const float corr0 = __expf(m0 - mn0), corr1 = __expf(m1 - mn1);
        m0 = mn0; m1 = mn1;

        float ps0 = 0.f, ps1 = 0.f;
        #pragma unroll
        for (int ni = 0; ni < 16; ni++) {
            s[ni][0] = __expf(s[ni][0] - m0); ps0 += s[ni][0];
            s[ni][1] = __expf(s[ni][1] - m0); ps0 += s[ni][1];
            s[ni][2] = __expf(s[ni][2] - m1); ps1 += s[ni][2];
            s[ni][3] = __expf(s[ni][3] - m1); ps1 += s[ni][3];
        }
        ps0 += __shfl_xor_sync(~0u, ps0, 1); ps0 += __shfl_xor_sync(~0u, ps0, 2);
        ps1 += __shfl_xor_sync(~0u, ps1, 1); ps1 += __shfl_xor_sync(~0u, ps1, 2);
        l0 = l0 * corr0 + ps0;
        l1 = l1 * corr1 + ps1;

        #pragma unroll
        for (int ni = 0; ni < 8; ni++) {
            accO[ni][0] *= corr0; accO[ni][1] *= corr0;
            accO[ni][2] *= corr1; accO[ni][3] *= corr1;
        }

        // ---- P (fp16) -> smem (warp-private rows)
        #pragma unroll
        for (int ni = 0; ni < 16; ni++) {
            const int col = ni * 8 + lr * 2;
            *(__half2*)&Ps[rowA * VSH + col]       = __floats2half2_rn(s[ni][0], s[ni][1]);
            *(__half2*)&Ps[(rowA + 8) * VSH + col] = __floats2half2_rn(s[ni][2], s[ni][3]);
        }
        __syncwarp();

        // ---- O += P V  (kv = 128 -> 8 k-steps of 16)
        #pragma unroll
        for (int c2 = 0; c2 < 8; c2++) {
            const int kb = c2 * 16 + 2 * lr;
            const uint32_t a0 = *(const uint32_t*)&Ps[rowA * VSH + kb];
            const uint32_t a1 = *(const uint32_t*)&Ps[(rowA + 8) * VSH + kb];
            const uint32_t a2 = *(const uint32_t*)&Ps[rowA * VSH + kb + 8];
            const uint32_t a3 = *(const uint32_t*)&Ps[(rowA + 8) * VSH + kb + 8];
            #pragma unroll
            for (int ni = 0; ni < 8; ni++) {
                const int n0 = ni * 8 + lq;
                const uint32_t b0 = *(const uint32_t*)&Vs[n0 * VSH + kb];
                const uint32_t b1 = *(const uint32_t*)&Vs[n0 * VSH + kb + 8];
                mma_f16(accO[ni][0], accO[ni][1], accO[ni][2], accO[ni][3],
                        a0, a1, a2, a3, b0, b1);
            }
        }
    }

    // ---- epilogue
    const float il0 = 1.f / l0, il1 = 1.f / l1;
    const int r0 = zb * S_ + qb * 128 + w * 16 + lq;
    #pragma unroll
    for (int ni = 0; ni < 8; ni++) {
        const int col = zh * 64 + ni * 8 + lr * 2;
        *(__half2*)&attno[(size_t)r0 * D_ + col] =
            __floats2half2_rn(accO[ni][0] * il0, accO[ni][1] * il0);
        *(__half2*)&attno[(size_t)(r0 + 8) * D_ + col] =
            __floats2half2_rn(accO[ni][2] * il1, accO[ni][3] * il1);
    }
}

// ===========================================================================
// RMSNorm: fp32 in -> half out
// ===========================================================================
__global__ void rmsnorm_h(const float* __restrict__ x, const float* __restrict__ w,
                          __half* __restrict__ y, float eps)
{
    const int row = blockIdx.x;
    const float* xr = x + (size_t)row * D_;
    float v[4];
    float s = 0.f;
    #pragma unroll
    for (int i = 0; i < 4; i++) { v[i] = xr[threadIdx.x + 256 * i]; s += v[i] * v[i]; }
    #pragma unroll
    for (int o = 16; o > 0; o >>= 1) s += __shfl_xor_sync(~0u, s, o);
    __shared__ float red[8];
    if ((threadIdx.x & 31) == 0) red[threadIdx.x >> 5] = s;
    __syncthreads();
    if (threadIdx.x < 8) {
        float t = red[threadIdx.x];
        #pragma unroll
        for (int o = 4; o > 0; o >>= 1) t += __shfl_xor_sync(0xffu, t, o);
        if (threadIdx.x == 0) red[0] = t;
    }
    __syncthreads();
    const float inv = rsqrtf(red[0] / (float)D_ + eps);
    __half* yr = y + (size_t)row * D_;
    #pragma unroll
    for (int i = 0; i < 4; i++)
        yr[threadIdx.x + 256 * i] = __float2half_rn(v[i] * inv * w[threadIdx.x + 256 * i]);
}

// ===========================================================================
// Gating — from raw fp32 h2 (exact path)
// ===========================================================================
__global__ void gate_k(const float* __restrict__ h2, const float* __restrict__ n2w,
                       const float* __restrict__ gw,
                       const float* __restrict__ gb, const float* __restrict__ grw,
                       float* __restrict__ g)
{
    const int n    = blockIdx.x * 4 + (threadIdx.x >> 5);
    const int lane = threadIdx.x & 31;
    const float* xr = h2 + (size_t)n * D_;
    float acc[E_];
    float ssx = 0.f;
    #pragma unroll
    for (int e = 0; e < E_; e++) acc[e] = 0.f;
    for (int d = lane; d < D_; d += 32) {
        const float xv = xr[d];
        ssx += xv * xv;
        const float xw = xv * n2w[d];
        #pragma unroll
        for (int e = 0; e < E_; e++) acc[e] += xw * gw[e * D_ + d];
    }
    #pragma unroll
    for (int o = 16; o > 0; o >>= 1) ssx += __shfl_xor_sync(~0u, ssx, o);
    #pragma unroll
    for (int e = 0; e < E_; e++)
        #pragma unroll
        for (int o = 16; o > 0; o >>= 1) acc[e] += __shfl_xor_sync(~0u, acc[e], o);
    if (lane == 0) {
        const float invr = rsqrtf(ssx / (float)D_ + 1e-8f);
        float l[E_], ss = 0.f;
        #pragma unroll
        for (int e = 0; e < E_; e++) { l[e] = acc[e] * invr + gb[e]; ss += l[e] * l[e]; }
        const float inv = rsqrtf(ss / (float)E_ + 1.1920929e-7f);
        float m = -INFINITY;
        #pragma unroll
        for (int e = 0; e < E_; e++) { l[e] = l[e] * inv * grw[e] * 2.0f; m = fmaxf(m, l[e]); }
        float sum = 0.f, mx = 0.f;
        #pragma unroll
        for (int e = 0; e < E_; e++) {
            const float ex = __expf(l[e] - m);
            sum += ex; mx = fmaxf(mx, ex);
        }
        const float top = mx / sum;
        g[n] = top / (top + 1e-6f);
    }
}

// ===========================================================================
// Batched transpose -> half: out[z][c][r] = half(in[z][r][c])
// ===========================================================================
template<typename Tin>
__global__ void transpose_h(const Tin* __restrict__ in, __half* __restrict__ out,
                            int ldin, int ldout,
                            int zDiv, long zi1, long zi2, long zo1, long zo2)
{
    __shared__ float t[32][33];
    const int z = blockIdx.z;
    const int zb = z / zDiv, zh = z - zb * zDiv;
    in  += (size_t)zb * zi1 + (size_t)zh * zi2;
    out += (size_t)zb * zo1 + (size_t)zh * zo2;
    const int c0 = blockIdx.x * 32, r0 = blockIdx.y * 32;
    #pragma unroll
    for (int i = 0; i < 4; i++)
        t[threadIdx.y + i * 8][threadIdx.x] =
            (float)in[(size_t)(r0 + threadIdx.y + i * 8) * ldin + c0 + threadIdx.x];
    __syncthreads();
    #pragma unroll
    for (int i = 0; i < 4; i++)
        out[(size_t)(c0 + threadIdx.y + i * 8) * ldout + r0 + threadIdx.x] =
            __float2half_rn(t[threadIdx.x][threadIdx.y + i * 8]);
}

// ===========================================================================
// fp32 -> half copy
// ===========================================================================
__global__ void f2h_k(const float* __restrict__ in, __half* __restrict__ out, int n)
{
    for (int i = blockIdx.x * blockDim.x + threadIdx.x; i < n; i += gridDim.x * blockDim.x)
        out[i] = __float2half_rn(in[i]);
}

// ===========================================================================
// Launch
// ===========================================================================
static constexpr int GEMM_SMEM = (2 * 128 * 40 + 2 * 128 * 40) * 2;   // 40960 B

extern "C" void kernel_launch(void* const* d_in, const int* in_sizes, int n_in,
                              void* d_out, int out_size)
{
    const float* x      = (const float*)d_in[0];
    const float* w_qkv  = (const float*)d_in[1];
    const float* w_out  = (const float*)d_in[2];
    const float* norm1w = (const float*)d_in[3];
    const float* norm2w = (const float*)d_in[4];
    const float* gate_w = (const float*)d_in[5];
    const float* gate_b = (const float*)d_in[6];
    const float* gate_rw= (const float*)d_in[7];
    const float* w1     = (const float*)d_in[8];
    const float* w2     = (const float*)d_in[9];
    float* out = (float*)d_out;

    __half *hn1, *wqkvr, *woutr, *qkv, *vt, *attno, *hn2, *w1t, *w2t, *act;
    float *h2, *gate;
    cudaGetSymbolAddress((void**)&hn1,    g_hn1);
    cudaGetSymbolAddress((void**)&wqkvr,  g_wqkvr);
    cudaGetSymbolAddress((void**)&woutr,  g_woutr);
    cudaGetSymbolAddress((void**)&qkv,    g_qkv);
    cudaGetSymbolAddress((void**)&vt,     g_vt);
    cudaGetSymbolAddress((void**)&attno,  g_attno);
    cudaGetSymbolAddress((void**)&h2,     g_h2);
    cudaGetSymbolAddress((void**)&hn2,    g_hn2);
    cudaGetSymbolAddress((void**)&gate,   g_gate);
    cudaGetSymbolAddress((void**)&w1t,    g_w1t);
    cudaGetSymbolAddress((void**)&w2t,    g_w2t);
    cudaGetSymbolAddress((void**)&act,    g_act);

    cudaFuncSetAttribute(gemm_f16<0>,     cudaFuncAttributeMaxDynamicSharedMemorySize, GEMM_SMEM);
    cudaFuncSetAttribute(gemm_f16<1>,     cudaFuncAttributeMaxDynamicSharedMemorySize, GEMM_SMEM);
    cudaFuncSetAttribute(gemm_f16<2>,     cudaFuncAttributeMaxDynamicSharedMemorySize, GEMM_SMEM);
    cudaFuncSetAttribute(moe1_swiglu_f16, cudaFuncAttributeMaxDynamicSharedMemorySize, GEMM_SMEM);
    cudaFuncSetAttribute(flash_attn_f16,  cudaFuncAttributeMaxDynamicSharedMemorySize, FA_SMEM);

    // --- weight prep (round to fp16; transpose w1/w2 to [N,K]) ---
    f2h_k<<<2048, 256>>>(w_qkv, wqkvr, 3 * D_ * D_);
    f2h_k<<<1024, 256>>>(w_out, woutr, D_ * D_);
    transpose_h<float><<<dim3(FF1_ / 32, D_ / 32, E_), dim3(32, 8)>>>(
        w1, w1t, FF1_, D_, 1, (long)D_ * FF1_, 0, (long)D_ * FF1_, 0);
    transpose_h<float><<<dim3(D_ / 32, KMOE2 / 32, 1), dim3(32, 8)>>>(
        w2, w2t, D_, KMOE2, 1, 0, 0, 0, 0);

    // --- 1) rmsnorm1 ---
    rmsnorm_h<<<NTOK, 256>>>(x, norm1w, hn1, 1e-8f);

    // --- 2) QKV: [4096,3072](half) = hn1 x wqkvr^T ---
    gemm_f16<0><<<dim3(3 * D_ / 128, NTOK / 128), 256, GEMM_SMEM>>>(
        hn1, wqkvr, qkv, nullptr, nullptr,
        NTOK, 3 * D_, D_, D_, D_, 3 * D_);

    // --- 3) V transpose (half -> half) ---
    transpose_h<__half><<<dim3(DH_ / 32, S_ / 32, B_ * H_), dim3(32, 8)>>>(
        qkv + 2 * D_, vt, 3 * D_, S_,
        H_, (long)S_ * 3 * D_, (long)DH_,
        (long)H_ * DH_ * S_, (long)DH_ * S_);

    // --- 4-6) fused flash attention ---
    flash_attn_f16<<<dim3(S_ / 128, B_ * H_), 256, FA_SMEM>>>(qkv, vt, attno);

    // --- 7) h2 = x + O w_out^T ---
    gemm_f16<1><<<dim3(D_ / 128, NTOK / 128), 256, GEMM_SMEM>>>(
        attno, woutr, h2, x, nullptr,
        NTOK, D_, D_, D_, D_, D_);

    // --- 8) rmsnorm2 + gate ---
    rmsnorm_h<<<NTOK, 256>>>(h2, norm2w, hn2, 1e-8f);
    gate_k<<<NTOK / 4, 128>>>(h2, norm2w, gate_w, gate_b, gate_rw, gate);

    // --- 9+10) fused MoE1 + SwiGLU -> act (half) [4096, 16384] ---
    moe1_swiglu_f16<<<dim3(FF2_ / 64, NTOK / 128, E_), 256, GEMM_SMEM>>>(
        hn2, w1t, act);

    // --- 11) MoE2: out = h2 + (act x w2t^T) * g[n] ---
    gemm_f16<2><<<dim3(D_ / 128, NTOK / 128), 256, GEMM_SMEM>>>(
        act, w2t, out, h2, gate,
        NTOK, D_, KMOE2, KMOE2, KMOE2, D_);

    (void)in_sizes; (void)n_in; (void)out_size;
}

// round 9
// speedup vs baseline: 1.8884x; 1.1211x over previous
#include <cuda_runtime.h>
#include <cuda_fp16.h>
#include <cstdint>
#include <cmath>

// ===========================================================================
// Problem constants
// ===========================================================================
static constexpr int B_   = 4;
static constexpr int S_   = 1024;
static constexpr int D_   = 1024;
static constexpr int H_   = 16;
static constexpr int DH_  = 64;
static constexpr int E_   = 8;
static constexpr int FF1_ = 4096;
static constexpr int FF2_ = 2048;
static constexpr int NTOK = B_ * S_;        // 4096
static constexpr int KMOE2 = E_ * FF2_;     // 16384

// ===========================================================================
// Scratch
// ===========================================================================
__device__ __half g_hn1  [(size_t)NTOK * D_];
__device__ __half g_wqkvr[(size_t)3 * D_ * D_];
__device__ __half g_woutr[(size_t)D_ * D_];
__device__ __half g_qkv  [(size_t)NTOK * 3 * D_];
__device__ __half g_vt   [(size_t)B_ * H_ * DH_ * S_];
__device__ __half g_attno[(size_t)NTOK * D_];
__device__ float  g_h2   [(size_t)NTOK * D_];
__device__ __half g_hn2  [(size_t)NTOK * D_];
__device__ float  g_gate [NTOK];
__device__ __half g_w1t  [(size_t)E_ * FF1_ * D_];
__device__ __half g_w2t  [(size_t)D_ * KMOE2];
__device__ __half g_act  [(size_t)NTOK * KMOE2];

// ===========================================================================
// Helpers
// ===========================================================================
__device__ __forceinline__ uint32_t smem_u32(const void* p) {
    uint32_t a;
    asm("{ .reg .u64 t; cvta.to.shared.u64 t, %1; cvt.u32.u64 %0, t; }" : "=r"(a) : "l"(p));
    return a;
}

#define CP16(dst, src) \
    asm volatile("cp.async.cg.shared.global [%0], [%1], 16;" :: "r"(dst), "l"(src))
#define CP_COMMIT()  asm volatile("cp.async.commit_group;" ::: "memory")
#define CP_WAIT1()   asm volatile("cp.async.wait_group 1;" ::: "memory")
#define CP_WAIT0()   asm volatile("cp.async.wait_group 0;" ::: "memory")

#define LDSM4(r0, r1, r2, r3, addr) \
    asm volatile("ldmatrix.sync.aligned.m8n8.x4.shared.b16 {%0,%1,%2,%3}, [%4];" \
        : "=r"(r0), "=r"(r1), "=r"(r2), "=r"(r3) : "r"(addr))

__device__ __forceinline__ void mma_f16(float& c0, float& c1, float& c2, float& c3,
                                        uint32_t a0, uint32_t a1, uint32_t a2, uint32_t a3,
                                        uint32_t b0, uint32_t b1)
{
    asm volatile(
        "mma.sync.aligned.m16n8k16.row.col.f32.f16.f16.f32 "
        "{%0,%1,%2,%3}, {%4,%5,%6,%7}, {%8,%9}, {%0,%1,%2,%3};"
        : "+f"(c0), "+f"(c1), "+f"(c2), "+f"(c3)
        : "r"(a0), "r"(a1), "r"(a2), "r"(a3), "r"(b0), "r"(b1));
}

// SMEM geometry (halves): rows padded to 40 halves = 80 B.
static constexpr int ROWH = 40;
static constexpr int ASTG = 128 * ROWH;   // halves per A stage
static constexpr int BSTG = 128 * ROWH;
static constexpr int GEMM_SMEM = (2 * ASTG + 2 * BSTG) * 2;   // 40960 B

// Per-thread ldmatrix address offsets (bytes, relative to tile base).
__device__ __forceinline__ uint32_t ldsm_a_off(int warp_m, int lane) {
    return ((uint32_t)(warp_m * 32 + (lane & 15)) * ROWH + (uint32_t)((lane >> 4) & 1) * 8) * 2;
}
__device__ __forceinline__ uint32_t ldsm_b_off(int warp_n, int pair, int lane) {
    return ((uint32_t)(warp_n * 64 + pair * 16 + ((lane >> 4) & 1) * 8 + (lane & 7)) * ROWH
            + (uint32_t)((lane >> 3) & 1) * 8) * 2;
}

// ===========================================================================
// fp16 NT GEMM: C[M,N] = A[M,K](half,K-major) * B[N,K](half,K-major)^T
//   EPI 0: C(half) = acc   EPI 1: C(float) = acc + Res
//   EPI 2: C(float) = Res + acc * Gvec[row]
// Block 128x128x32; 8 warps (4m x 2n); warp tile 32x64; ldmatrix fragments.
// ===========================================================================
template<int EPI>
__global__ void __launch_bounds__(256)
gemm_f16(const __half* __restrict__ A, const __half* __restrict__ B,
         void* __restrict__ Cv, const float* __restrict__ Res,
         const float* __restrict__ Gvec,
         int M, int N, int K, int lda, int ldb, int ldc)
{
    extern __shared__ __align__(16) __half smh[];
    const uint32_t sbase = smem_u32(smh);
    const int tid = threadIdx.x, wid = tid >> 5, lane = tid & 31;
    const int warp_m = wid & 3, warp_n = wid >> 2;

    const int bm = blockIdx.y * 128;
    const int bn = blockIdx.x * 128;
    A += (size_t)bm * lda;
    B += (size_t)bn * ldb;

    const int nk = K / 32;

    auto loadA = [&](int s, int kt) {
        const __half* base = A + kt * 32;
        const uint32_t dbase = sbase + (uint32_t)(s * ASTG) * 2;
        #pragma unroll
        for (int i = 0; i < 2; i++) {
            const int c = tid + i * 256;
            const int row = c >> 2, kc = c & 3;
            CP16(dbase + (uint32_t)row * 80 + (uint32_t)kc * 16,
                 base + (size_t)row * lda + kc * 8);
        }
    };
    auto loadB = [&](int s, int kt) {
        const __half* base = B + kt * 32;
        const uint32_t dbase = sbase + (uint32_t)(2 * ASTG + s * BSTG) * 2;
        #pragma unroll
        for (int i = 0; i < 2; i++) {
            const int c = tid + i * 256;
            const int row = c >> 2, kc = c & 3;
            CP16(dbase + (uint32_t)row * 80 + (uint32_t)kc * 16,
                 base + (size_t)row * ldb + kc * 8);
        }
    };

    float acc[2][8][4];
    #pragma unroll
    for (int mi = 0; mi < 2; mi++)
        #pragma unroll
        for (int ni = 0; ni < 8; ni++)
            #pragma unroll
            for (int j = 0; j < 4; j++) acc[mi][ni][j] = 0.f;

    loadA(0, 0); loadB(0, 0); CP_COMMIT();

    const uint32_t aOff = ldsm_a_off(warp_m, lane);
    uint32_t bOff[4];
    #pragma unroll
    for (int p = 0; p < 4; p++) bOff[p] = ldsm_b_off(warp_n, p, lane);

    const int lq = lane >> 2;
    const int lr = lane & 3;

    for (int kt = 0; kt < nk; kt++) {
        const int cs = kt & 1;
        if (kt + 1 < nk) {
            loadA(cs ^ 1, kt + 1); loadB(cs ^ 1, kt + 1); CP_COMMIT();
            CP_WAIT1();
        } else {
            CP_WAIT0();
        }
        __syncthreads();

        const uint32_t aS = sbase + (uint32_t)(cs * ASTG) * 2 + aOff;
        const uint32_t bS = sbase + (uint32_t)(2 * ASTG + cs * BSTG) * 2;

        #pragma unroll
        for (int ks = 0; ks < 2; ks++) {
            uint32_t a[2][4];
            LDSM4(a[0][0], a[0][1], a[0][2], a[0][3], aS + ks * 32);
            LDSM4(a[1][0], a[1][1], a[1][2], a[1][3], aS + 16 * ROWH * 2 + ks * 32);
            uint32_t b[8][2];
            #pragma unroll
            for (int p = 0; p < 4; p++)
                LDSM4(b[2 * p][0], b[2 * p][1], b[2 * p + 1][0], b[2 * p + 1][1],
                      bS + bOff[p] + ks * 32);
            #pragma unroll
            for (int mi = 0; mi < 2; mi++)
                #pragma unroll
                for (int ni = 0; ni < 8; ni++)
                    mma_f16(acc[mi][ni][0], acc[mi][ni][1], acc[mi][ni][2], acc[mi][ni][3],
                            a[mi][0], a[mi][1], a[mi][2], a[mi][3],
                            b[ni][0], b[ni][1]);
        }
        __syncthreads();
    }

    #pragma unroll
    for (int mi = 0; mi < 2; mi++) {
        const int row0 = bm + warp_m * 32 + mi * 16 + lq;
        float gv0 = 1.f, gv1 = 1.f;
        if (EPI == 2) { gv0 = Gvec[row0]; gv1 = Gvec[row0 + 8]; }
        #pragma unroll
        for (int ni = 0; ni < 8; ni++) {
            const int col = bn + warp_n * 64 + ni * 8 + lr * 2;
            const size_t i0 = (size_t)row0 * ldc + col;
            const size_t i1 = (size_t)(row0 + 8) * ldc + col;
            if (EPI == 0) {
                __half* C = (__half*)Cv;
                *(__half2*)&C[i0] = __floats2half2_rn(acc[mi][ni][0], acc[mi][ni][1]);
                *(__half2*)&C[i1] = __floats2half2_rn(acc[mi][ni][2], acc[mi][ni][3]);
            } else if (EPI == 1) {
                float* C = (float*)Cv;
                float2 r0 = *(const float2*)&Res[i0];
                float2 r1 = *(const float2*)&Res[i1];
                float2 o0 = {acc[mi][ni][0] + r0.x, acc[mi][ni][1] + r0.y};
                float2 o1 = {acc[mi][ni][2] + r1.x, acc[mi][ni][3] + r1.y};
                *(float2*)&C[i0] = o0;
                *(float2*)&C[i1] = o1;
            } else {
                float* C = (float*)Cv;
                float2 r0 = *(const float2*)&Res[i0];
                float2 r1 = *(const float2*)&Res[i1];
                float2 o0 = {r0.x + acc[mi][ni][0] * gv0, r0.y + acc[mi][ni][1] * gv0};
                float2 o1 = {r1.x + acc[mi][ni][2] * gv1, r1.y + acc[mi][ni][3] * gv1};
                *(float2*)&C[i0] = o0;
                *(float2*)&C[i1] = o1;
            }
        }
    }
}

// ===========================================================================
// Fused MoE1 + SwiGLU (fp16 + ldmatrix): 128 tokens x 64 act-cols per CTA.
// B tile interleaves a/b halves by 8-row groups (even ni = a, odd ni = b).
// Grid: (FF2/64, NTOK/128, E)
// ===========================================================================
__global__ void __launch_bounds__(256)
moe1_swiglu_f16(const __half* __restrict__ hn2, const __half* __restrict__ w1t,
                __half* __restrict__ act)
{
    extern __shared__ __align__(16) __half smh[];
    const uint32_t sbase = smem_u32(smh);
    const int tid = threadIdx.x, wid = tid >> 5, lane = tid & 31;
    const int warp_m = wid & 3, warp_n = wid >> 2;

    const int e    = blockIdx.z;
    const int bn_a = blockIdx.x * 64;
    const int bm   = blockIdx.y * 128;

    const __half* A  = hn2 + (size_t)bm * D_;
    const __half* Be = w1t + (size_t)e * FF1_ * D_;

    const int nk = D_ / 32;

    auto loadA = [&](int s, int kt) {
        const __half* base = A + kt * 32;
        const uint32_t dbase = sbase + (uint32_t)(s * ASTG) * 2;
        #pragma unroll
        for (int i = 0; i < 2; i++) {
            const int c = tid + i * 256;
            const int row = c >> 2, kc = c & 3;
            CP16(dbase + (uint32_t)row * 80 + (uint32_t)kc * 16,
                 base + (size_t)row * D_ + kc * 8);
        }
    };
    auto loadB = [&](int s, int kt) {
        const uint32_t dbase = sbase + (uint32_t)(2 * ASTG + s * BSTG) * 2;
        #pragma unroll
        for (int i = 0; i < 2; i++) {
            const int c = tid + i * 256;
            const int row = c >> 2, kc = c & 3;
            const int half_ = (row >> 3) & 1;
            const int coll = ((row >> 4) << 3) + (row & 7);
            const int wrow = bn_a + coll + half_ * FF2_;
            CP16(dbase + (uint32_t)row * 80 + (uint32_t)kc * 16,
                 Be + (size_t)wrow * D_ + kt * 32 + kc * 8);
        }
    };

    float acc[2][8][4];
    #pragma unroll
    for (int mi = 0; mi < 2; mi++)
        #pragma unroll
        for (int ni = 0; ni < 8; ni++)
            #pragma unroll
            for (int j = 0; j < 4; j++) acc[mi][ni][j] = 0.f;

    loadA(0, 0); loadB(0, 0); CP_COMMIT();

    const uint32_t aOff = ldsm_a_off(warp_m, lane);
    uint32_t bOff[4];
    #pragma unroll
    for (int p = 0; p < 4; p++) bOff[p] = ldsm_b_off(warp_n, p, lane);

    const int lq = lane >> 2;
    const int lr = lane & 3;

    for (int kt = 0; kt < nk; kt++) {
        const int cs = kt & 1;
        if (kt + 1 < nk) {
            loadA(cs ^ 1, kt + 1); loadB(cs ^ 1, kt + 1); CP_COMMIT();
            CP_WAIT1();
        } else {
            CP_WAIT0();
        }
        __syncthreads();

        const uint32_t aS = sbase + (uint32_t)(cs * ASTG) * 2 + aOff;
        const uint32_t bS = sbase + (uint32_t)(2 * ASTG + cs * BSTG) * 2;

        #pragma unroll
        for (int ks = 0; ks < 2; ks++) {
            uint32_t a[2][4];
            LDSM4(a[0][0], a[0][1], a[0][2], a[0][3], aS + ks * 32);
            LDSM4(a[1][0], a[1][1], a[1][2], a[1][3], aS + 16 * ROWH * 2 + ks * 32);
            uint32_t b[8][2];
            #pragma unroll
            for (int p = 0; p < 4; p++)
                LDSM4(b[2 * p][0], b[2 * p][1], b[2 * p + 1][0], b[2 * p + 1][1],
                      bS + bOff[p] + ks * 32);
            #pragma unroll
            for (int mi = 0; mi < 2; mi++)
                #pragma unroll
                for (int ni = 0; ni < 8; ni++)
                    mma_f16(acc[mi][ni][0], acc[mi][ni][1], acc[mi][ni][2], acc[mi][ni][3],
                            a[mi][0], a[mi][1], a[mi][2], a[mi][3],
                            b[ni][0], b[ni][1]);
        }
        __syncthreads();
    }

    #pragma unroll
    for (int mi = 0; mi < 2; mi++) {
        const int row0 = bm + warp_m * 32 + mi * 16 + lq;
        #pragma unroll
        for (int p = 0; p < 4; p++) {
            const float* av = acc[mi][2 * p];
            const float* bv = acc[mi][2 * p + 1];
            const float v0 = av[0] * bv[0] / (1.f + __expf(-bv[0]));
            const float v1 = av[1] * bv[1] / (1.f + __expf(-bv[1]));
            const float v2 = av[2] * bv[2] / (1.f + __expf(-bv[2]));
            const float v3 = av[3] * bv[3] / (1.f + __expf(-bv[3]));
            const int col = e * FF2_ + bn_a + warp_n * 32 + p * 8 + lr * 2;
            *(__half2*)&act[(size_t)row0 * KMOE2 + col] = __floats2half2_rn(v0, v1);
            *(__half2*)&act[(size_t)(row0 + 8) * KMOE2 + col] = __floats2half2_rn(v2, v3);
        }
    }
}

// ===========================================================================
// Flash attention fp16: fused QK^T + online softmax + PV.
// Grid (8 q-blocks, 64 bh). 8 warps; warp owns 16 q-rows x full 128-kv tile.
// ===========================================================================
static constexpr int KSH = 72;
static constexpr int VSH = 136;
static constexpr int FA_SMEM = (128 * KSH + 64 * VSH + 128 * VSH) * 2;  // 70656 B

__global__ void __launch_bounds__(256)
flash_attn_f16(const __half* __restrict__ qkv, const __half* __restrict__ vt,
               __half* __restrict__ attno)
{
    extern __shared__ __align__(16) __half smh[];
    __half* Ks = smh;
    __half* Vs = smh + 128 * KSH;
    __half* Ps = smh + 128 * KSH + 64 * VSH;
    const uint32_t sb  = smem_u32(smh);
    const uint32_t KsB = sb;
    const uint32_t VsB = sb + 128 * KSH * 2;

    const int tid = threadIdx.x, w = tid >> 5, lane = tid & 31;
    const int lq = lane >> 2, lr = lane & 3;
    const int qb = blockIdx.x;
    const int z  = blockIdx.y;
    const int zb = z >> 4, zh = z & 15;

    const __half* Qbase = qkv + (size_t)zb * S_ * 3 * D_ + zh * 64;
    const __half* Kbase = Qbase + D_;
    const __half* Vt    = vt + (size_t)z * DH_ * S_;

    uint32_t qf[4][4];
    {
        const int r0 = qb * 128 + w * 16 + lq;
        const __half* q0 = Qbase + (size_t)r0 * 3 * D_;
        const __half* q1 = Qbase + (size_t)(r0 + 8) * 3 * D_;
        #pragma unroll
        for (int c = 0; c < 4; c++) {
            qf[c][0] = *(const uint32_t*)&q0[c * 16 + 2 * lr];
            qf[c][1] = *(const uint32_t*)&q1[c * 16 + 2 * lr];
            qf[c][2] = *(const uint32_t*)&q0[c * 16 + 2 * lr + 8];
            qf[c][3] = *(const uint32_t*)&q1[c * 16 + 2 * lr + 8];
        }
    }

    float m0 = -1e30f, m1 = -1e30f, l0 = 0.f, l1 = 0.f;
    float accO[8][4];
    #pragma unroll
    for (int ni = 0; ni < 8; ni++)
        #pragma unroll
        for (int j = 0; j < 4; j++) accO[ni][j] = 0.f;

    const int rowA = w * 16 + lq;

    for (int j = 0; j < 8; j++) {
        __syncthreads();
        #pragma unroll
        for (int i = 0; i < 4; i++) {
            const int c = tid + i * 256;
            const int row = c >> 3, kc = c & 7;
            CP16(KsB + (uint32_t)row * (KSH * 2) + (uint32_t)kc * 16,
                 Kbase + (size_t)(j * 128 + row) * 3 * D_ + kc * 8);
        }
        #pragma unroll
        for (int i = 0; i < 4; i++) {
            const int c = tid + i * 256;
            const int row = c >> 4, kc = c & 15;
            CP16(VsB + (uint32_t)row * (VSH * 2) + (uint32_t)kc * 16,
                 Vt + (size_t)row * S_ + j * 128 + kc * 8);
        }
        CP_COMMIT(); CP_WAIT0();
        __syncthreads();

        float s[16][4];
        #pragma unroll
        for (int ni = 0; ni < 16; ni++)
            #pragma unroll
            for (int jj = 0; jj < 4; jj++) s[ni][jj] = 0.f;

        #pragma unroll
        for (int c = 0; c < 4; c++) {
            const int kb = c * 16 + 2 * lr;
            #pragma unroll
            for (int ni = 0; ni < 16; ni++) {
                const int n0 = ni * 8 + lq;
                const uint32_t b0 = *(const uint32_t*)&Ks[n0 * KSH + kb];
                const uint32_t b1 = *(const uint32_t*)&Ks[n0 * KSH + kb + 8];
                mma_f16(s[ni][0], s[ni][1], s[ni][2], s[ni][3],
                        qf[c][0], qf[c][1], qf[c][2], qf[c][3], b0, b1);
            }
        }

        float rm0 = -1e30f, rm1 = -1e30f;
        #pragma unroll
        for (int ni = 0; ni < 16; ni++) {
            s[ni][0] *= 0.125f; s[ni][1] *= 0.125f;
            s[ni][2] *= 0.125f; s[ni][3] *= 0.125f;
            rm0 = fmaxf(rm0, fmaxf(s[ni][0], s[ni][1]));
            rm1 = fmaxf(rm1, fmaxf(s[ni][2], s[ni][3]));
        }
        rm0 = fmaxf(rm0, __shfl_xor_sync(~0u, rm0, 1));
        rm0 = fmaxf(rm0, __shfl_xor_sync(~0u, rm0, 2));
        rm1 = fmaxf(rm1, __shfl_xor_sync(~0u, rm1, 1));
        rm1 = fmaxf(rm1, __shfl_xor_sync(~0u, rm1, 2));

        const float mn0 = fmaxf(m0, rm0), mn1 = fmaxf(m1, rm1);
        const float corr0 = __expf(m0 - mn0), corr1 = __expf(m1 - mn1);
        m0 = mn0; m1 = mn1;

        float ps0 = 0.f, ps1 = 0.f;
        #pragma unroll
        for (int ni = 0; ni < 16; ni++) {
            s[ni][0] = __expf(s[ni][0] - m0); ps0 += s[ni][0];
            s[ni][1] = __expf(s[ni][1] - m0); ps0 += s[ni][1];
            s[ni][2] = __expf(s[ni][2] - m1); ps1 += s[ni][2];
            s[ni][3] = __expf(s[ni][3] - m1); ps1 += s[ni][3];
        }
        ps0 += __shfl_xor_sync(~0u, ps0, 1); ps0 += __shfl_xor_sync(~0u, ps0, 2);
        ps1 += __shfl_xor_sync(~0u, ps1, 1); ps1 += __shfl_xor_sync(~0u, ps1, 2);
        l0 = l0 * corr0 + ps0;
        l1 = l1 * corr1 + ps1;

        #pragma unroll
        for (int ni = 0; ni < 8; ni++) {
            accO[ni][0] *= corr0; accO[ni][1] *= corr0;
            accO[ni][2] *= corr1; accO[ni][3] *= corr1;
        }

        #pragma unroll
        for (int ni = 0; ni < 16; ni++) {
            const int col = ni * 8 + lr * 2;
            *(__half2*)&Ps[rowA * VSH + col]       = __floats2half2_rn(s[ni][0], s[ni][1]);
            *(__half2*)&Ps[(rowA + 8) * VSH + col] = __floats2half2_rn(s[ni][2], s[ni][3]);
        }
        __syncwarp();

        #pragma unroll
        for (int c2 = 0; c2 < 8; c2++) {
            const int kb = c2 * 16 + 2 * lr;
            const uint32_t a0 = *(const uint32_t*)&Ps[rowA * VSH + kb];
            const uint32_t a1 = *(const uint32_t*)&Ps[(rowA + 8) * VSH + kb];
            const uint32_t a2 = *(const uint32_t*)&Ps[rowA * VSH + kb + 8];
            const uint32_t a3 = *(const uint32_t*)&Ps[(rowA + 8) * VSH + kb + 8];
            #pragma unroll
            for (int ni = 0; ni < 8; ni++) {
                const int n0 = ni * 8 + lq;
                const uint32_t b0 = *(const uint32_t*)&Vs[n0 * VSH + kb];
                const uint32_t b1 = *(const uint32_t*)&Vs[n0 * VSH + kb + 8];
                mma_f16(accO[ni][0], accO[ni][1], accO[ni][2], accO[ni][3],
                        a0, a1, a2, a3, b0, b1);
            }
        }
    }

    const float il0 = 1.f / l0, il1 = 1.f / l1;
    const int r0 = zb * S_ + qb * 128 + w * 16 + lq;
    #pragma unroll
    for (int ni = 0; ni < 8; ni++) {
        const int col = zh * 64 + ni * 8 + lr * 2;
        *(__half2*)&attno[(size_t)r0 * D_ + col] =
            __floats2half2_rn(accO[ni][0] * il0, accO[ni][1] * il0);
        *(__half2*)&attno[(size_t)(r0 + 8) * D_ + col] =
            __floats2half2_rn(accO[ni][2] * il1, accO[ni][3] * il1);
    }
}

// ===========================================================================
// RMSNorm: fp32 in -> half out
// ===========================================================================
__global__ void rmsnorm_h(const float* __restrict__ x, const float* __restrict__ w,
                          __half* __restrict__ y, float eps)
{
    const int row = blockIdx.x;
    const float* xr = x + (size_t)row * D_;
    float v[4];
    float s = 0.f;
    #pragma unroll
    for (int i = 0; i < 4; i++) { v[i] = xr[threadIdx.x + 256 * i]; s += v[i] * v[i]; }
    #pragma unroll
    for (int o = 16; o > 0; o >>= 1) s += __shfl_xor_sync(~0u, s, o);
    __shared__ float red[8];
    if ((threadIdx.x & 31) == 0) red[threadIdx.x >> 5] = s;
    __syncthreads();
    if (threadIdx.x < 8) {
        float t = red[threadIdx.x];
        #pragma unroll
        for (int o = 4; o > 0; o >>= 1) t += __shfl_xor_sync(0xffu, t, o);
        if (threadIdx.x == 0) red[0] = t;
    }
    __syncthreads();
    const float inv = rsqrtf(red[0] / (float)D_ + eps);
    __half* yr = y + (size_t)row * D_;
    #pragma unroll
    for (int i = 0; i < 4; i++)
        yr[threadIdx.x + 256 * i] = __float2half_rn(v[i] * inv * w[threadIdx.x + 256 * i]);
}

// ===========================================================================
// Gating — from raw fp32 h2 (exact path)
// ===========================================================================
__global__ void gate_k(const float* __restrict__ h2, const float* __restrict__ n2w,
                       const float* __restrict__ gw,
                       const float* __restrict__ gb, const float* __restrict__ grw,
                       float* __restrict__ g)
{
    const int n    = blockIdx.x * 4 + (threadIdx.x >> 5);
    const int lane = threadIdx.x & 31;
    const float* xr = h2 + (size_t)n * D_;
    float acc[E_];
    float ssx = 0.f;
    #pragma unroll
    for (int e = 0; e < E_; e++) acc[e] = 0.f;
    for (int d = lane; d < D_; d += 32) {
        const float xv = xr[d];
        ssx += xv * xv;
        const float xw = xv * n2w[d];
        #pragma unroll
        for (int e = 0; e < E_; e++) acc[e] += xw * gw[e * D_ + d];
    }
    #pragma unroll
    for (int o = 16; o > 0; o >>= 1) ssx += __shfl_xor_sync(~0u, ssx, o);
    #pragma unroll
    for (int e = 0; e < E_; e++)
        #pragma unroll
        for (int o = 16; o > 0; o >>= 1) acc[e] += __shfl_xor_sync(~0u, acc[e], o);
    if (lane == 0) {
        const float invr = rsqrtf(ssx / (float)D_ + 1e-8f);
        float l[E_], ss = 0.f;
        #pragma unroll
        for (int e = 0; e < E_; e++) { l[e] = acc[e] * invr + gb[e]; ss += l[e] * l[e]; }
        const float inv = rsqrtf(ss / (float)E_ + 1.1920929e-7f);
        float m = -INFINITY;
        #pragma unroll
        for (int e = 0; e < E_; e++) { l[e] = l[e] * inv * grw[e] * 2.0f; m = fmaxf(m, l[e]); }
        float sum = 0.f, mx = 0.f;
        #pragma unroll
        for (int e = 0; e < E_; e++) {
            const float ex = __expf(l[e] - m);
            sum += ex; mx = fmaxf(mx, ex);
        }
        const float top = mx / sum;
        g[n] = top / (top + 1e-6f);
    }
}

// ===========================================================================
// Batched transpose -> half
// ===========================================================================
template<typename Tin>
__global__ void transpose_h(const Tin* __restrict__ in, __half* __restrict__ out,
                            int ldin, int ldout,
                            int zDiv, long zi1, long zi2, long zo1, long zo2)
{
    __shared__ float t[32][33];
    const int z = blockIdx.z;
    const int zb = z / zDiv, zh = z - zb * zDiv;
    in  += (size_t)zb * zi1 + (size_t)zh * zi2;
    out += (size_t)zb * zo1 + (size_t)zh * zo2;
    const int c0 = blockIdx.x * 32, r0 = blockIdx.y * 32;
    #pragma unroll
    for (int i = 0; i < 4; i++)
        t[threadIdx.y + i * 8][threadIdx.x] =
            (float)in[(size_t)(r0 + threadIdx.y + i * 8) * ldin + c0 + threadIdx.x];
    __syncthreads();
    #pragma unroll
    for (int i = 0; i < 4; i++)
        out[(size_t)(c0 + threadIdx.y + i * 8) * ldout + r0 + threadIdx.x] =
            __float2half_rn(t[threadIdx.x][threadIdx.y + i * 8]);
}

// ===========================================================================
// fp32 -> half copy
// ===========================================================================
__global__ void f2h_k(const float* __restrict__ in, __half* __restrict__ out, int n)
{
    for (int i = blockIdx.x * blockDim.x + threadIdx.x; i < n; i += gridDim.x * blockDim.x)
        out[i] = __float2half_rn(in[i]);
}

// ===========================================================================
// Launch
// ===========================================================================
extern "C" void kernel_launch(void* const* d_in, const int* in_sizes, int n_in,
                              void* d_out, int out_size)
{
    const float* x      = (const float*)d_in[0];
    const float* w_qkv  = (const float*)d_in[1];
    const float* w_out  = (const float*)d_in[2];
    const float* norm1w = (const float*)d_in[3];
    const float* norm2w = (const float*)d_in[4];
    const float* gate_w = (const float*)d_in[5];
    const float* gate_b = (const float*)d_in[6];
    const float* gate_rw= (const float*)d_in[7];
    const float* w1     = (const float*)d_in[8];
    const float* w2     = (const float*)d_in[9];
    float* out = (float*)d_out;

    __half *hn1, *wqkvr, *woutr, *qkv, *vt, *attno, *hn2, *w1t, *w2t, *act;
    float *h2, *gate;
    cudaGetSymbolAddress((void**)&hn1,    g_hn1);
    cudaGetSymbolAddress((void**)&wqkvr,  g_wqkvr);
    cudaGetSymbolAddress((void**)&woutr,  g_woutr);
    cudaGetSymbolAddress((void**)&qkv,    g_qkv);
    cudaGetSymbolAddress((void**)&vt,     g_vt);
    cudaGetSymbolAddress((void**)&attno,  g_attno);
    cudaGetSymbolAddress((void**)&h2,     g_h2);
    cudaGetSymbolAddress((void**)&hn2,    g_hn2);
    cudaGetSymbolAddress((void**)&gate,   g_gate);
    cudaGetSymbolAddress((void**)&w1t,    g_w1t);
    cudaGetSymbolAddress((void**)&w2t,    g_w2t);
    cudaGetSymbolAddress((void**)&act,    g_act);

    cudaFuncSetAttribute(gemm_f16<0>,     cudaFuncAttributeMaxDynamicSharedMemorySize, GEMM_SMEM);
    cudaFuncSetAttribute(gemm_f16<1>,     cudaFuncAttributeMaxDynamicSharedMemorySize, GEMM_SMEM);
    cudaFuncSetAttribute(gemm_f16<2>,     cudaFuncAttributeMaxDynamicSharedMemorySize, GEMM_SMEM);
    cudaFuncSetAttribute(moe1_swiglu_f16, cudaFuncAttributeMaxDynamicSharedMemorySize, GEMM_SMEM);
    cudaFuncSetAttribute(flash_attn_f16,  cudaFuncAttributeMaxDynamicSharedMemorySize, FA_SMEM);

    // --- weight prep (fp16; transpose w1/w2 to [N,K]) ---
    f2h_k<<<2048, 256>>>(w_qkv, wqkvr, 3 * D_ * D_);
    f2h_k<<<1024, 256>>>(w_out, woutr, D_ * D_);
    transpose_h<float><<<dim3(FF1_ / 32, D_ / 32, E_), dim3(32, 8)>>>(
        w1, w1t, FF1_, D_, 1, (long)D_ * FF1_, 0, (long)D_ * FF1_, 0);
    transpose_h<float><<<dim3(D_ / 32, KMOE2 / 32, 1), dim3(32, 8)>>>(
        w2, w2t, D_, KMOE2, 1, 0, 0, 0, 0);

    // --- 1) rmsnorm1 ---
    rmsnorm_h<<<NTOK, 256>>>(x, norm1w, hn1, 1e-8f);

    // --- 2) QKV ---
    gemm_f16<0><<<dim3(3 * D_ / 128, NTOK / 128), 256, GEMM_SMEM>>>(
        hn1, wqkvr, qkv, nullptr, nullptr,
        NTOK, 3 * D_, D_, D_, D_, 3 * D_);

    // --- 3) V transpose ---
    transpose_h<__half><<<dim3(DH_ / 32, S_ / 32, B_ * H_), dim3(32, 8)>>>(
        qkv + 2 * D_, vt, 3 * D_, S_,
        H_, (long)S_ * 3 * D_, (long)DH_,
        (long)H_ * DH_ * S_, (long)DH_ * S_);

    // --- 4-6) fused flash attention ---
    flash_attn_f16<<<dim3(S_ / 128, B_ * H_), 256, FA_SMEM>>>(qkv, vt, attno);

    // --- 7) h2 = x + O w_out^T ---
    gemm_f16<1><<<dim3(D_ / 128, NTOK / 128), 256, GEMM_SMEM>>>(
        attno, woutr, h2, x, nullptr,
        NTOK, D_, D_, D_, D_, D_);

    // --- 8) rmsnorm2 + gate ---
    rmsnorm_h<<<NTOK, 256>>>(h2, norm2w, hn2, 1e-8f);
    gate_k<<<NTOK / 4, 128>>>(h2, norm2w, gate_w, gate_b, gate_rw, gate);

    // --- 9+10) fused MoE1 + SwiGLU -> act (half) ---
    moe1_swiglu_f16<<<dim3(FF2_ / 64, NTOK / 128, E_), 256, GEMM_SMEM>>>(
        hn2, w1t, act);

    // --- 11) MoE2: out = h2 + (act x w2t^T) * g[n] ---
    gemm_f16<2><<<dim3(D_ / 128, NTOK / 128), 256, GEMM_SMEM>>>(
        act, w2t, out, h2, gate,
        NTOK, D_, KMOE2, KMOE2, KMOE2, D_);

    (void)in_sizes; (void)n_in; (void)out_size;
}